// round 6
// baseline (speedup 1.0000x reference)
#include <cuda_runtime.h>
#include <math.h>
#include <stdint.h>

// ---------------- Problem constants ----------------
#define LSEQ   2048
#define DMODEL 4096
#define NH     128
#define DP     64
#define NG     8
#define DN     128
#define CSZ    128
#define NCH    (LSEQ / CSZ)
#define KCONV  4
#define DINTER 8192
#define DCONV  10240
#define DPROJ  18560
#define RMS_EPS 1e-5f

// ---------------- Scratch ----------------
__device__ float g_proj[LSEQ * DPROJ];
__device__ float g_xbc[LSEQ * DCONV];
__device__ float g_dt[LSEQ * NH];
__device__ float g_acs[NCH * NH * CSZ];
__device__ float g_alast[NCH * NH];
__device__ float g_cbt[NCH * NG * CSZ * CSZ];
__device__ float g_states[NCH * NH * DP * DN];
__device__ float g_prefix[NCH * NH * DP * DN];
__device__ float g_y[LSEQ * DINTER];
// tf32-bit copies of GEMM operands (converted once per call)
__device__ float g_hst[LSEQ * DMODEL];
__device__ float g_w1t[DPROJ * DMODEL];
__device__ float g_w2t[DMODEL * DINTER];

// ---------------- helpers ----------------
__device__ __forceinline__ uint32_t f2tf32(float f) {
    uint32_t r;
    asm("cvt.rna.tf32.f32 %0, %1;" : "=r"(r) : "f"(f));
    return r;
}
__device__ __forceinline__ void mma_tf32(float c[4], const uint32_t a[4], const uint32_t b[2]) {
    asm volatile(
        "mma.sync.aligned.m16n8k8.row.col.f32.tf32.tf32.f32 "
        "{%0,%1,%2,%3}, {%4,%5,%6,%7}, {%8,%9}, {%0,%1,%2,%3};"
        : "+f"(c[0]), "+f"(c[1]), "+f"(c[2]), "+f"(c[3])
        : "r"(a[0]), "r"(a[1]), "r"(a[2]), "r"(a[3]), "r"(b[0]), "r"(b[1]));
}
__device__ __forceinline__ float fast_silu(float x) {
    float t;
    asm("tanh.approx.f32 %0, %1;" : "=f"(t) : "f"(x * 0.5f));
    return 0.5f * x * (1.f + t);
}
__device__ __forceinline__ uint32_t smem_u32(const void* p) {
    uint32_t a;
    asm("{ .reg .u64 t; cvta.to.shared.u64 t, %1; cvt.u32.u64 %0, t; }" : "=r"(a) : "l"(p));
    return a;
}
__device__ __forceinline__ void cp_async16(uint32_t saddr, const void* gaddr) {
    asm volatile("cp.async.cg.shared.global [%0], [%1], 16;" :: "r"(saddr), "l"(gaddr));
}
#define CP_COMMIT() asm volatile("cp.async.commit_group;" ::: "memory")
#define CP_WAIT(n)  asm volatile("cp.async.wait_group %0;" :: "n"(n) : "memory")

// ---------------- tf32 pre-conversion (elementwise, float4) ----------------
__global__ void cvt_tf32_kernel(const float* __restrict__ in, float* __restrict__ out, int n4)
{
    int i = blockIdx.x * blockDim.x + threadIdx.x;
    if (i >= n4) return;
    float4 v = ((const float4*)in)[i];
    uint4 o;
    o.x = f2tf32(v.x); o.y = f2tf32(v.y); o.z = f2tf32(v.z); o.w = f2tf32(v.w);
    ((uint4*)out)[i] = o;
}

// ---------------- tf32 GEMM, cp.async 3-stage, operands pre-converted ----------------
// C[M,Nd] = A[M,Kd]*B[Nd,Kd]^T. BM=BN=128, BK=16, 256 threads, warp tile 64x32.
#define GSTAGES 3
#define ROWW    20
#define TILEW   (128 * ROWW)
#define GEMM_DSMEM (GSTAGES * 2 * TILEW * 4)

__global__ __launch_bounds__(256, 2) void gemm_tf32_kernel(
    const float* __restrict__ A, const float* __restrict__ B, float* __restrict__ C,
    int Nd, int Kd)
{
    extern __shared__ float smf[];
    float* const Abuf = smf;
    float* const Bbuf = smf + GSTAGES * TILEW;
    const uint32_t sbaseA = smem_u32(Abuf);
    const uint32_t sbaseB = smem_u32(Bbuf);

    const int tid  = threadIdx.x;
    const int lane = tid & 31, warp = tid >> 5;
    const int wm = (warp >> 2) * 64;
    const int wn = (warp & 3) * 32;
    const int g  = lane >> 2, tq = lane & 3;
    const int bm = blockIdx.y * 128, bn = blockIdx.x * 128;

    const int r0 = tid >> 2, q = (tid & 3) * 4;
    const float* Ag0 = A + (size_t)(bm + r0) * Kd + q;
    const float* Ag1 = Ag0 + (size_t)64 * Kd;
    const float* Bg0 = B + (size_t)(bn + r0) * Kd + q;
    const float* Bg1 = Bg0 + (size_t)64 * Kd;
    const uint32_t swA0 = sbaseA + (uint32_t)(r0 * ROWW + q) * 4;
    const uint32_t swA1 = swA0 + 64 * ROWW * 4;
    const uint32_t swB0 = sbaseB + (uint32_t)(r0 * ROWW + q) * 4;
    const uint32_t swB1 = swB0 + 64 * ROWW * 4;

    const int KT = Kd >> 4;

#pragma unroll
    for (int s = 0; s < GSTAGES - 1; s++) {
        const uint32_t so = (uint32_t)(s * TILEW * 4);
        const size_t ko = (size_t)s * 16;
        cp_async16(swA0 + so, Ag0 + ko);
        cp_async16(swA1 + so, Ag1 + ko);
        cp_async16(swB0 + so, Bg0 + ko);
        cp_async16(swB1 + so, Bg1 + ko);
        CP_COMMIT();
    }

    float acc[4][4][4];
#pragma unroll
    for (int mt = 0; mt < 4; mt++)
#pragma unroll
        for (int nt = 0; nt < 4; nt++)
#pragma unroll
            for (int qq = 0; qq < 4; qq++) acc[mt][nt][qq] = 0.f;

    int buf = 0;
    for (int kt = 0; kt < KT; kt++) {
        CP_WAIT(GSTAGES - 2);
        __syncthreads();

        const int pf = kt + GSTAGES - 1;
        if (pf < KT) {
            const int pb = pf % GSTAGES;
            const uint32_t so = (uint32_t)(pb * TILEW * 4);
            const size_t ko = (size_t)pf * 16;
            cp_async16(swA0 + so, Ag0 + ko);
            cp_async16(swA1 + so, Ag1 + ko);
            cp_async16(swB0 + so, Bg0 + ko);
            cp_async16(swB1 + so, Bg1 + ko);
        }
        CP_COMMIT();

        const uint32_t* As = (const uint32_t*)(Abuf + buf * TILEW);
        const uint32_t* Bs = (const uint32_t*)(Bbuf + buf * TILEW);
#pragma unroll
        for (int ks = 0; ks < 2; ks++) {
            const int ko = ks * 8;
            uint32_t af[4][4], bf[4][2];
#pragma unroll
            for (int mt = 0; mt < 4; mt++) {
                const int m0 = wm + mt * 16;
                af[mt][0] = As[(m0 + g    ) * ROWW + ko + tq];
                af[mt][1] = As[(m0 + g + 8) * ROWW + ko + tq];
                af[mt][2] = As[(m0 + g    ) * ROWW + ko + tq + 4];
                af[mt][3] = As[(m0 + g + 8) * ROWW + ko + tq + 4];
            }
#pragma unroll
            for (int nt = 0; nt < 4; nt++) {
                const int n0 = wn + nt * 8;
                bf[nt][0] = Bs[(n0 + g) * ROWW + ko + tq];
                bf[nt][1] = Bs[(n0 + g) * ROWW + ko + tq + 4];
            }
#pragma unroll
            for (int mt = 0; mt < 4; mt++)
#pragma unroll
                for (int nt = 0; nt < 4; nt++)
                    mma_tf32(acc[mt][nt], af[mt], bf[nt]);
        }
        buf = (buf + 1) % GSTAGES;
        __syncthreads();
    }

#pragma unroll
    for (int mt = 0; mt < 4; mt++) {
#pragma unroll
        for (int nt = 0; nt < 4; nt++) {
            const int row = bm + wm + mt * 16 + g;
            const int col = bn + wn + nt * 8 + 2 * tq;
            *(float2*)&C[(size_t)row * Nd + col]       = make_float2(acc[mt][nt][0], acc[mt][nt][1]);
            *(float2*)&C[(size_t)(row + 8) * Nd + col] = make_float2(acc[mt][nt][2], acc[mt][nt][3]);
        }
    }
}

// ---------------- Depthwise causal conv (K=4) + SiLU ----------------
__global__ void conv_silu_kernel(const float* __restrict__ conv_w, const float* __restrict__ conv_b)
{
    int idx = blockIdx.x * blockDim.x + threadIdx.x;
    if (idx >= LSEQ * DCONV) return;
    int t = idx / DCONV, c = idx % DCONV;
    float acc = conv_b[c];
    const float* w = conv_w + c * KCONV;
#pragma unroll
    for (int k = 0; k < KCONV; k++) {
        int tt = t + k - (KCONV - 1);
        if (tt >= 0) acc += w[k] * g_proj[(size_t)tt * DPROJ + DINTER + c];
    }
    g_xbc[idx] = fast_silu(acc);
}

// ---------------- dt softplus + per-chunk cumsum of A*dt ----------------
__global__ __launch_bounds__(CSZ) void dt_scan_kernel(
    const float* __restrict__ dt_bias, const float* __restrict__ A_log)
{
    int c = blockIdx.x, h = blockIdx.y, l = threadIdx.x;
    int t = c * CSZ + l;
    float raw = g_proj[(size_t)t * DPROJ + DINTER + DCONV + h] + dt_bias[h];
    float dtp = (raw > 0.f) ? (raw + log1pf(__expf(-raw))) : log1pf(__expf(raw));
    g_dt[t * NH + h] = dtp;
    float a = -__expf(A_log[h]) * dtp;

    __shared__ float s[CSZ];
    s[l] = a;
    __syncthreads();
#pragma unroll
    for (int off = 1; off < CSZ; off <<= 1) {
        float v = (l >= off) ? s[l - off] : 0.f;
        __syncthreads();
        s[l] += v;
        __syncthreads();
    }
    g_acs[(c * NH + h) * CSZ + l] = s[l];
    if (l == CSZ - 1) g_alast[c * NH + h] = s[l];
}

// ---------------- CBt[c][g][s][l] = sum_n C[l,n]*B[s,n] ----------------
__global__ __launch_bounds__(256) void cb_kernel()
{
    int c = blockIdx.x, g = blockIdx.y;
    int tid = threadIdx.x, tx = tid & 15, ty = tid >> 4;
    __shared__ float Csn[16][CSZ];
    __shared__ float Bsn[16][CSZ];
    float acc[8][8];
#pragma unroll
    for (int i = 0; i < 8; i++)
#pragma unroll
        for (int j = 0; j < 8; j++) acc[i][j] = 0.f;

    const float* Cg = g_xbc + DINTER + NG * DN + g * DN;
    const float* Bg = g_xbc + DINTER + g * DN;

    for (int n0 = 0; n0 < DN; n0 += 16) {
        for (int i = tid; i < CSZ * 4; i += 256) {
            int r = i >> 2, q = i & 3;
            const size_t row = (size_t)(c * CSZ + r) * DCONV + n0 + q * 4;
            float4 cv = *(const float4*)(Cg + row);
            float4 bv = *(const float4*)(Bg + row);
            Csn[q * 4 + 0][r] = cv.x; Csn[q * 4 + 1][r] = cv.y;
            Csn[q * 4 + 2][r] = cv.z; Csn[q * 4 + 3][r] = cv.w;
            Bsn[q * 4 + 0][r] = bv.x; Bsn[q * 4 + 1][r] = bv.y;
            Bsn[q * 4 + 2][r] = bv.z; Bsn[q * 4 + 3][r] = bv.w;
        }
        __syncthreads();
#pragma unroll
        for (int nn = 0; nn < 16; nn++) {
            float4 c0 = *(const float4*)&Csn[nn][tx * 8];
            float4 c1 = *(const float4*)&Csn[nn][tx * 8 + 4];
            float4 b0 = *(const float4*)&Bsn[nn][ty * 8];
            float4 b1 = *(const float4*)&Bsn[nn][ty * 8 + 4];
            float cl[8] = {c0.x, c0.y, c0.z, c0.w, c1.x, c1.y, c1.z, c1.w};
            float bs[8] = {b0.x, b0.y, b0.z, b0.w, b1.x, b1.y, b1.z, b1.w};
#pragma unroll
            for (int si = 0; si < 8; si++)
#pragma unroll
                for (int li = 0; li < 8; li++) acc[si][li] += cl[li] * bs[si];
        }
        __syncthreads();
    }
    float* out = g_cbt + (size_t)(c * NG + g) * CSZ * CSZ;
#pragma unroll
    for (int si = 0; si < 8; si++) {
        int s = ty * 8 + si;
        *(float4*)(out + (size_t)s * CSZ + tx * 8)     = make_float4(acc[si][0], acc[si][1], acc[si][2], acc[si][3]);
        *(float4*)(out + (size_t)s * CSZ + tx * 8 + 4) = make_float4(acc[si][4], acc[si][5], acc[si][6], acc[si][7]);
    }
}

// ---------------- Y_diag + D residual ----------------
__global__ __launch_bounds__(256) void ydiag_kernel(const float* __restrict__ Dparam)
{
    int c = blockIdx.x, h = blockIdx.y, g = h >> 4;
    int tid = threadIdx.x, tx = tid & 15, ty = tid >> 4;
    __shared__ float xs[CSZ][DP];
    __shared__ float Ms[CSZ][17];
    __shared__ float acsS[CSZ];
    __shared__ float dts[CSZ];

    for (int i = tid; i < CSZ * DP / 4; i += 256) {
        int r = i >> 4, q = i & 15;
        *(float4*)&xs[r][q * 4] =
            *(const float4*)(g_xbc + (size_t)(c * CSZ + r) * DCONV + h * DP + q * 4);
    }
    if (tid < CSZ) {
        dts[tid]  = g_dt[(c * CSZ + tid) * NH + h];
        acsS[tid] = g_acs[(c * NH + h) * CSZ + tid];
    }
    __syncthreads();

    float acc[8][4];
#pragma unroll
    for (int i = 0; i < 8; i++)
#pragma unroll
        for (int j = 0; j < 4; j++) acc[i][j] = 0.f;

    const float* cbBase = g_cbt + (size_t)(c * NG + g) * CSZ * CSZ;
    const int ss_row = tid >> 4;
    const int lg     = tid & 15;

    for (int s0 = 0; s0 < CSZ; s0 += 16) {
        {
            const int s = s0 + ss_row;
            const float as  = acsS[s];
            const float dsv = dts[s];
            const float* cbRow = cbBase + (size_t)s * CSZ;
#pragma unroll
            for (int k = 0; k < 8; k++) {
                const int l = lg * 8 + k;
                float f = 0.f;
                if (s <= l) f = cbRow[l] * __expf(acsS[l] - as) * dsv;
                Ms[l][ss_row] = f;
            }
        }
        __syncthreads();

#pragma unroll
        for (int ss = 0; ss < 16; ss++) {
            const int s = s0 + ss;
            float msv[8];
#pragma unroll
            for (int i = 0; i < 8; i++) msv[i] = Ms[ty * 8 + i][ss];
            float4 xv4 = *(const float4*)&xs[s][tx * 4];
#pragma unroll
            for (int i = 0; i < 8; i++) {
                acc[i][0] += msv[i] * xv4.x;
                acc[i][1] += msv[i] * xv4.y;
                acc[i][2] += msv[i] * xv4.z;
                acc[i][3] += msv[i] * xv4.w;
            }
        }
        __syncthreads();
    }

    const float dcoef = Dparam[h];
#pragma unroll
    for (int i = 0; i < 8; i++) {
        int l = ty * 8 + i;
        float4 xr = *(const float4*)&xs[l][tx * 4];
        float4 o = make_float4(acc[i][0] + dcoef * xr.x, acc[i][1] + dcoef * xr.y,
                               acc[i][2] + dcoef * xr.z, acc[i][3] + dcoef * xr.w);
        *(float4*)(g_y + (size_t)(c * CSZ + l) * DINTER + h * DP + tx * 4) = o;
    }
}

// ---------------- Local chunk states ----------------
__global__ __launch_bounds__(256) void states_kernel()
{
    int c = blockIdx.x, h = blockIdx.y, g = h >> 4;
    int tid = threadIdx.x, tx = tid & 15, ty = tid >> 4;
    __shared__ float Bsh[32][DN];
    __shared__ float xds[32][DP];
    __shared__ float dec[32];
    float acc[4][8];
#pragma unroll
    for (int i = 0; i < 4; i++)
#pragma unroll
        for (int j = 0; j < 8; j++) acc[i][j] = 0.f;

    const float al = g_alast[c * NH + h];
    for (int l0 = 0; l0 < CSZ; l0 += 32) {
        for (int i = tid; i < 32 * DN / 4; i += 256) {
            int r = i >> 5, q = i & 31;
            *(float4*)&Bsh[r][q * 4] = *(const float4*)(
                g_xbc + (size_t)(c * CSZ + l0 + r) * DCONV + DINTER + g * DN + q * 4);
        }
        for (int i = tid; i < 32 * DP / 4; i += 256) {
            int r = i >> 4, q = i & 15;
            int t = c * CSZ + l0 + r;
            float4 xv = *(const float4*)(g_xbc + (size_t)t * DCONV + h * DP + q * 4);
            float d = g_dt[t * NH + h];
            xv.x *= d; xv.y *= d; xv.z *= d; xv.w *= d;
            *(float4*)&xds[r][q * 4] = xv;
        }
        if (tid < 32) dec[tid] = __expf(al - g_acs[(c * NH + h) * CSZ + l0 + tid]);
        __syncthreads();
#pragma unroll 8
        for (int ll = 0; ll < 32; ll++) {
            float d = dec[ll];
            float4 b0 = *(const float4*)&Bsh[ll][tx * 8];
            float4 b1 = *(const float4*)&Bsh[ll][tx * 8 + 4];
            float bb[8] = {b0.x, b0.y, b0.z, b0.w, b1.x, b1.y, b1.z, b1.w};
            float4 xv = *(const float4*)&xds[ll][ty * 4];
            float xp[4] = {xv.x * d, xv.y * d, xv.z * d, xv.w * d};
#pragma unroll
            for (int pi = 0; pi < 4; pi++)
#pragma unroll
                for (int nj = 0; nj < 8; nj++) acc[pi][nj] += xp[pi] * bb[nj];
        }
        __syncthreads();
    }
    float* out = g_states + (size_t)(c * NH + h) * DP * DN;
#pragma unroll
    for (int pi = 0; pi < 4; pi++) {
        int p = ty * 4 + pi;
        *(float4*)(out + (size_t)p * DN + tx * 8)     = make_float4(acc[pi][0], acc[pi][1], acc[pi][2], acc[pi][3]);
        *(float4*)(out + (size_t)p * DN + tx * 8 + 4) = make_float4(acc[pi][4], acc[pi][5], acc[pi][6], acc[pi][7]);
    }
}

// ---------------- Inter-chunk scan ----------------
__global__ void prefix_kernel()
{
    int idx = blockIdx.x * blockDim.x + threadIdx.x;
    if (idx >= NH * DP * DN) return;
    int h = idx >> 13;
    float s = 0.f;
#pragma unroll
    for (int c = 0; c < NCH; c++) {
        size_t off = (size_t)c * NH * DP * DN + idx;
        g_prefix[off] = s;
        s = __expf(g_alast[c * NH + h]) * s + g_states[off];
    }
}

// ---------------- Y_off ----------------
__global__ __launch_bounds__(256) void yoff_kernel()
{
    int c = blockIdx.x, h = blockIdx.y, g = h >> 4;
    int tid = threadIdx.x, tx = tid & 15, ty = tid >> 4;
    __shared__ float Cs[CSZ][32];
    __shared__ float Pf[DP][33];
    __shared__ float acsS[CSZ];
    if (tid < CSZ) acsS[tid] = g_acs[(c * NH + h) * CSZ + tid];

    float acc[8][4];
#pragma unroll
    for (int i = 0; i < 8; i++)
#pragma unroll
        for (int j = 0; j < 4; j++) acc[i][j] = 0.f;

    for (int n0 = 0; n0 < DN; n0 += 32) {
        for (int i = tid; i < CSZ * 8; i += 256) {
            int r = i >> 3, q = i & 7;
            *(float4*)&Cs[r][q * 4] = *(const float4*)(
                g_xbc + (size_t)(c * CSZ + r) * DCONV + DINTER + NG * DN + g * DN + n0 + q * 4);
        }
        for (int i = tid; i < DP * 8; i += 256) {
            int r = i >> 3, q = i & 7;
            float4 v = *(const float4*)(
                g_prefix + ((size_t)(c * NH + h) * DP + r) * DN + n0 + q * 4);
            Pf[r][q * 4 + 0] = v.x; Pf[r][q * 4 + 1] = v.y;
            Pf[r][q * 4 + 2] = v.z; Pf[r][q * 4 + 3] = v.w;
        }
        __syncthreads();
#pragma unroll 8
        for (int nn = 0; nn < 32; nn++) {
            float cl[8], pv[4];
#pragma unroll
            for (int i = 0; i < 8; i++) cl[i] = Cs[ty * 8 + i][nn];
#pragma unroll
            for (int j = 0; j < 4; j++) pv[j] = Pf[tx * 4 + j][nn];
#pragma unroll
            for (int i = 0; i < 8; i++)
#pragma unroll
                for (int j = 0; j < 4; j++) acc[i][j] += cl[i] * pv[j];
        }
        __syncthreads();
    }
#pragma unroll
    for (int i = 0; i < 8; i++) {
        int l = ty * 8 + i;
        float e = __expf(acsS[l]);
        float* yp = g_y + (size_t)(c * CSZ + l) * DINTER + h * DP + tx * 4;
        float4 y = *(float4*)yp;
        y.x += e * acc[i][0]; y.y += e * acc[i][1];
        y.z += e * acc[i][2]; y.w += e * acc[i][3];
        *(float4*)yp = y;
    }
}

// ---------------- RMSNorm * norm_w * silu(gate); output tf32-rounded for GEMM2 ----------------
__global__ __launch_bounds__(256) void rms_gate_kernel(const float* __restrict__ norm_w)
{
    int t = blockIdx.x, tid = threadIdx.x;
    const size_t base = (size_t)t * DINTER;
    float ss = 0.f;
    for (int i = tid; i < DINTER; i += 256) {
        float v = g_y[base + i];
        ss += v * v;
    }
    __shared__ float red[256];
    red[tid] = ss;
    __syncthreads();
#pragma unroll
    for (int o = 128; o > 0; o >>= 1) {
        if (tid < o) red[tid] += red[tid + o];
        __syncthreads();
    }
    float inv = rsqrtf(red[0] / (float)DINTER + RMS_EPS);
    for (int i = tid; i < DINTER; i += 256) {
        float v = g_y[base + i] * inv * norm_w[i];
        v *= fast_silu(g_proj[(size_t)t * DPROJ + i]);
        ((uint32_t*)g_y)[base + i] = f2tf32(v);   // tf32 bits (valid fp32) for GEMM2 A
    }
}

// ---------------- Launch ----------------
extern "C" void kernel_launch(void* const* d_in, const int* in_sizes, int n_in,
                              void* d_out, int out_size)
{
    (void)in_sizes; (void)n_in; (void)out_size;
    const float* hs         = (const float*)d_in[0];
    const float* in_proj_w  = (const float*)d_in[1];
    const float* conv_w     = (const float*)d_in[2];
    const float* conv_b     = (const float*)d_in[3];
    const float* dt_bias    = (const float*)d_in[4];
    const float* A_log      = (const float*)d_in[5];
    const float* Dp         = (const float*)d_in[6];
    const float* norm_w     = (const float*)d_in[7];
    const float* out_proj_w = (const float*)d_in[8];
    float* out = (float*)d_out;

    void *p_proj = nullptr, *p_y = nullptr, *p_hst = nullptr, *p_w1t = nullptr, *p_w2t = nullptr;
    cudaGetSymbolAddress(&p_proj, g_proj);
    cudaGetSymbolAddress(&p_y, g_y);
    cudaGetSymbolAddress(&p_hst, g_hst);
    cudaGetSymbolAddress(&p_w1t, g_w1t);
    cudaGetSymbolAddress(&p_w2t, g_w2t);

    cudaFuncSetAttribute(gemm_tf32_kernel, cudaFuncAttributeMaxDynamicSharedMemorySize, GEMM_DSMEM);

    // 0) pre-convert GEMM operands to tf32 bits
    {
        int n4;
        n4 = LSEQ * DMODEL / 4;
        cvt_tf32_kernel<<<(n4 + 255) / 256, 256>>>(hs, (float*)p_hst, n4);
        n4 = DPROJ * DMODEL / 4;
        cvt_tf32_kernel<<<(n4 + 255) / 256, 256>>>(in_proj_w, (float*)p_w1t, n4);
        n4 = DMODEL * DINTER / 4;
        cvt_tf32_kernel<<<(n4 + 255) / 256, 256>>>(out_proj_w, (float*)p_w2t, n4);
    }

    // 1) in-proj GEMM
    gemm_tf32_kernel<<<dim3(DPROJ / 128, LSEQ / 128), 256, GEMM_DSMEM>>>(
        (const float*)p_hst, (const float*)p_w1t, (float*)p_proj, DPROJ, DMODEL);
    // 2) causal depthwise conv + silu
    conv_silu_kernel<<<(LSEQ * DCONV + 255) / 256, 256>>>(conv_w, conv_b);
    // 3) dt softplus + per-chunk cumsum of A*dt
    dt_scan_kernel<<<dim3(NCH, NH), CSZ>>>(dt_bias, A_log);
    // 4) C·B^T per (chunk, group)
    cb_kernel<<<dim3(NCH, NG), 256>>>();
    // 5) intra-chunk output + D residual
    ydiag_kernel<<<dim3(NCH, NH), 256>>>(Dp);
    // 6) local chunk states
    states_kernel<<<dim3(NCH, NH), 256>>>();
    // 7) inter-chunk state scan
    prefix_kernel<<<(NH * DP * DN + 255) / 256, 256>>>();
    // 8) off-diagonal output
    yoff_kernel<<<dim3(NCH, NH), 256>>>();
    // 9) gated RMSNorm (writes tf32-rounded)
    rms_gate_kernel<<<LSEQ, 256>>>(norm_w);
    // 10) out-proj GEMM
    gemm_tf32_kernel<<<dim3(DMODEL / 128, LSEQ / 128), 256, GEMM_DSMEM>>>(
        (const float*)p_y, (const float*)p_w2t, out, DMODEL, DINTER);
}

// round 8
// speedup vs baseline: 1.2423x; 1.2423x over previous
#include <cuda_runtime.h>
#include <math.h>
#include <stdint.h>

// ---------------- Problem constants ----------------
#define LSEQ   2048
#define DMODEL 4096
#define NH     128
#define DP     64
#define NG     8
#define DN     128
#define CSZ    128
#define NCH    (LSEQ / CSZ)
#define KCONV  4
#define DINTER 8192
#define DCONV  10240
#define DPROJ  18560
#define RMS_EPS 1e-5f

// ---------------- Scratch ----------------
__device__ float g_proj[LSEQ * DPROJ];
__device__ float g_xbc[LSEQ * DCONV];
__device__ float g_dt[LSEQ * NH];
__device__ float g_acs[NCH * NH * CSZ];
__device__ float g_alast[NCH * NH];
__device__ float g_cbt[NCH * NG * CSZ * CSZ];
__device__ float g_states[NCH * NH * DP * DN];
__device__ float g_prefix[NCH * NH * DP * DN];
__device__ float g_y[LSEQ * DINTER];
__device__ float g_hst[LSEQ * DMODEL];
__device__ float g_w1t[DPROJ * DMODEL];
__device__ float g_w2t[DMODEL * DINTER];

// ---------------- helpers ----------------
__device__ __forceinline__ uint32_t f2tf32(float f) {
    uint32_t r;
    asm("cvt.rna.tf32.f32 %0, %1;" : "=r"(r) : "f"(f));
    return r;
}
__device__ __forceinline__ void mma_tf32(float c[4], const uint32_t a[4], const uint32_t b[2]) {
    asm volatile(
        "mma.sync.aligned.m16n8k8.row.col.f32.tf32.tf32.f32 "
        "{%0,%1,%2,%3}, {%4,%5,%6,%7}, {%8,%9}, {%0,%1,%2,%3};"
        : "+f"(c[0]), "+f"(c[1]), "+f"(c[2]), "+f"(c[3])
        : "r"(a[0]), "r"(a[1]), "r"(a[2]), "r"(a[3]), "r"(b[0]), "r"(b[1]));
}
__device__ __forceinline__ float fast_silu(float x) {
    float t;
    asm("tanh.approx.f32 %0, %1;" : "=f"(t) : "f"(x * 0.5f));
    return 0.5f * x * (1.f + t);
}
__device__ __forceinline__ uint32_t smem_u32(const void* p) {
    uint32_t a;
    asm("{ .reg .u64 t; cvta.to.shared.u64 t, %1; cvt.u32.u64 %0, t; }" : "=r"(a) : "l"(p));
    return a;
}
__device__ __forceinline__ void cp_async16(uint32_t saddr, const void* gaddr) {
    asm volatile("cp.async.cg.shared.global [%0], [%1], 16;" :: "r"(saddr), "l"(gaddr));
}
#define CP_COMMIT() asm volatile("cp.async.commit_group;" ::: "memory")
#define CP_WAIT(n)  asm volatile("cp.async.wait_group %0;" :: "n"(n) : "memory")

// ---------------- tf32 pre-conversion ----------------
__global__ void cvt_tf32_kernel(const float* __restrict__ in, float* __restrict__ out, int n4)
{
    int i = blockIdx.x * blockDim.x + threadIdx.x;
    if (i >= n4) return;
    float4 v = ((const float4*)in)[i];
    uint4 o;
    o.x = f2tf32(v.x); o.y = f2tf32(v.y); o.z = f2tf32(v.z); o.w = f2tf32(v.w);
    ((uint4*)out)[i] = o;
}

// ---------------- tf32 GEMM: BK=32, XOR-swizzled smem, 3 stages, 1 barrier/ktile ----------------
// C[M,Nd] = A[M,Kd]*B[Nd,Kd]^T. BM=BN=128, 256 threads, warp tile 64x32.
// Smem stage: 128 rows x 32 words per operand, 16B chunks placed at (c ^ (row&7)).
#define GSTAGES 3
#define STAGEW  (128 * 32)                      // words per operand per stage
#define GEMM_DSMEM (GSTAGES * 2 * STAGEW * 4)   // 98304 bytes

__global__ __launch_bounds__(256, 2) void gemm_tf32_kernel(
    const float* __restrict__ A, const float* __restrict__ B, float* __restrict__ C,
    int Nd, int Kd)
{
    extern __shared__ float smf[];
    float* const Abuf = smf;
    float* const Bbuf = smf + GSTAGES * STAGEW;
    const uint32_t sbaseA = smem_u32(Abuf);
    const uint32_t sbaseB = smem_u32(Bbuf);

    const int tid  = threadIdx.x;
    const int lane = tid & 31, warp = tid >> 5;
    const int wm = (warp >> 2) * 64;
    const int wn = (warp & 3) * 32;
    const int g  = lane >> 2, tq = lane & 3;
    const int bm = blockIdx.y * 128, bn = blockIdx.x * 128;

    // staging: thread handles rows r0+32j (j=0..3), chunk c (16B) within row
    const int r0 = tid >> 3, c = tid & 7;
    const uint32_t swoff = (uint32_t)((c ^ (r0 & 7)) << 4);   // same for all 4 rows
    const float* AgBase = A + (size_t)(bm + r0) * Kd + c * 4;
    const float* BgBase = B + (size_t)(bn + r0) * Kd + c * 4;
    const uint32_t sA0 = sbaseA + (uint32_t)(r0 * 128) + swoff;
    const uint32_t sB0 = sbaseB + (uint32_t)(r0 * 128) + swoff;

    const int KT = Kd >> 5;

#pragma unroll
    for (int s = 0; s < GSTAGES - 1; s++) {
        const uint32_t so = (uint32_t)(s * STAGEW * 4);
        const size_t ko = (size_t)s * 32;
#pragma unroll
        for (int j = 0; j < 4; j++) {
            cp_async16(sA0 + so + j * 32 * 128, AgBase + (size_t)(32 * j) * Kd + ko);
            cp_async16(sB0 + so + j * 32 * 128, BgBase + (size_t)(32 * j) * Kd + ko);
        }
        CP_COMMIT();
    }

    float acc[4][4][4];
#pragma unroll
    for (int mt = 0; mt < 4; mt++)
#pragma unroll
        for (int nt = 0; nt < 4; nt++)
#pragma unroll
            for (int qq = 0; qq < 4; qq++) acc[mt][nt][qq] = 0.f;

    int buf = 0;
    for (int kt = 0; kt < KT; kt++) {
        CP_WAIT(1);
        __syncthreads();

        const int pf = kt + GSTAGES - 1;
        if (pf < KT) {
            const int pb = pf % GSTAGES;
            const uint32_t so = (uint32_t)(pb * STAGEW * 4);
            const size_t ko = (size_t)pf * 32;
#pragma unroll
            for (int j = 0; j < 4; j++) {
                cp_async16(sA0 + so + j * 32 * 128, AgBase + (size_t)(32 * j) * Kd + ko);
                cp_async16(sB0 + so + j * 32 * 128, BgBase + (size_t)(32 * j) * Kd + ko);
            }
        }
        CP_COMMIT();

        const uint32_t* As = (const uint32_t*)(Abuf + buf * STAGEW);
        const uint32_t* Bs = (const uint32_t*)(Bbuf + buf * STAGEW);
#pragma unroll
        for (int ks = 0; ks < 4; ks++) {
            const int kq0 = ((2 * ks)     ^ g) * 4 + tq;   // swizzled word for k = 8ks + tq
            const int kq1 = ((2 * ks + 1) ^ g) * 4 + tq;   // swizzled word for k = 8ks + tq + 4
            uint32_t af[4][4], bf[4][2];
#pragma unroll
            for (int mt = 0; mt < 4; mt++) {
                const int m0 = wm + mt * 16;
                af[mt][0] = As[(m0 + g    ) * 32 + kq0];
                af[mt][1] = As[(m0 + g + 8) * 32 + kq0];
                af[mt][2] = As[(m0 + g    ) * 32 + kq1];
                af[mt][3] = As[(m0 + g + 8) * 32 + kq1];
            }
#pragma unroll
            for (int nt = 0; nt < 4; nt++) {
                const int n0 = wn + nt * 8;
                bf[nt][0] = Bs[(n0 + g) * 32 + kq0];
                bf[nt][1] = Bs[(n0 + g) * 32 + kq1];
            }
#pragma unroll
            for (int mt = 0; mt < 4; mt++)
#pragma unroll
                for (int nt = 0; nt < 4; nt++)
                    mma_tf32(acc[mt][nt], af[mt], bf[nt]);
        }
        buf = (buf + 1) % GSTAGES;
        // no trailing barrier: next iteration's top barrier protects buffer reuse
    }

#pragma unroll
    for (int mt = 0; mt < 4; mt++) {
#pragma unroll
        for (int nt = 0; nt < 4; nt++) {
            const int row = bm + wm + mt * 16 + g;
            const int col = bn + wn + nt * 8 + 2 * tq;
            *(float2*)&C[(size_t)row * Nd + col]       = make_float2(acc[mt][nt][0], acc[mt][nt][1]);
            *(float2*)&C[(size_t)(row + 8) * Nd + col] = make_float2(acc[mt][nt][2], acc[mt][nt][3]);
        }
    }
}

// ---------------- Depthwise causal conv (K=4) + SiLU ----------------
__global__ void conv_silu_kernel(const float* __restrict__ conv_w, const float* __restrict__ conv_b)
{
    int idx = blockIdx.x * blockDim.x + threadIdx.x;
    if (idx >= LSEQ * DCONV) return;
    int t = idx / DCONV, c = idx % DCONV;
    float acc = conv_b[c];
    const float* w = conv_w + c * KCONV;
#pragma unroll
    for (int k = 0; k < KCONV; k++) {
        int tt = t + k - (KCONV - 1);
        if (tt >= 0) acc += w[k] * g_proj[(size_t)tt * DPROJ + DINTER + c];
    }
    g_xbc[idx] = fast_silu(acc);
}

// ---------------- dt softplus + per-chunk cumsum of A*dt ----------------
__global__ __launch_bounds__(CSZ) void dt_scan_kernel(
    const float* __restrict__ dt_bias, const float* __restrict__ A_log)
{
    int c = blockIdx.x, h = blockIdx.y, l = threadIdx.x;
    int t = c * CSZ + l;
    float raw = g_proj[(size_t)t * DPROJ + DINTER + DCONV + h] + dt_bias[h];
    float dtp = (raw > 0.f) ? (raw + log1pf(__expf(-raw))) : log1pf(__expf(raw));
    g_dt[t * NH + h] = dtp;
    float a = -__expf(A_log[h]) * dtp;

    __shared__ float s[CSZ];
    s[l] = a;
    __syncthreads();
#pragma unroll
    for (int off = 1; off < CSZ; off <<= 1) {
        float v = (l >= off) ? s[l - off] : 0.f;
        __syncthreads();
        s[l] += v;
        __syncthreads();
    }
    g_acs[(c * NH + h) * CSZ + l] = s[l];
    if (l == CSZ - 1) g_alast[c * NH + h] = s[l];
}

// ---------------- CBt[c][g][s][l] = sum_n C[l,n]*B[s,n] ----------------
__global__ __launch_bounds__(256) void cb_kernel()
{
    int c = blockIdx.x, g = blockIdx.y;
    int tid = threadIdx.x, tx = tid & 15, ty = tid >> 4;
    __shared__ float Csn[16][CSZ];
    __shared__ float Bsn[16][CSZ];
    float acc[8][8];
#pragma unroll
    for (int i = 0; i < 8; i++)
#pragma unroll
        for (int j = 0; j < 8; j++) acc[i][j] = 0.f;

    const float* Cg = g_xbc + DINTER + NG * DN + g * DN;
    const float* Bg = g_xbc + DINTER + g * DN;

    for (int n0 = 0; n0 < DN; n0 += 16) {
        for (int i = tid; i < CSZ * 4; i += 256) {
            int r = i >> 2, q = i & 3;
            const size_t row = (size_t)(c * CSZ + r) * DCONV + n0 + q * 4;
            float4 cv = *(const float4*)(Cg + row);
            float4 bv = *(const float4*)(Bg + row);
            Csn[q * 4 + 0][r] = cv.x; Csn[q * 4 + 1][r] = cv.y;
            Csn[q * 4 + 2][r] = cv.z; Csn[q * 4 + 3][r] = cv.w;
            Bsn[q * 4 + 0][r] = bv.x; Bsn[q * 4 + 1][r] = bv.y;
            Bsn[q * 4 + 2][r] = bv.z; Bsn[q * 4 + 3][r] = bv.w;
        }
        __syncthreads();
#pragma unroll
        for (int nn = 0; nn < 16; nn++) {
            float4 c0 = *(const float4*)&Csn[nn][tx * 8];
            float4 c1 = *(const float4*)&Csn[nn][tx * 8 + 4];
            float4 b0 = *(const float4*)&Bsn[nn][ty * 8];
            float4 b1 = *(const float4*)&Bsn[nn][ty * 8 + 4];
            float cl[8] = {c0.x, c0.y, c0.z, c0.w, c1.x, c1.y, c1.z, c1.w};
            float bs[8] = {b0.x, b0.y, b0.z, b0.w, b1.x, b1.y, b1.z, b1.w};
#pragma unroll
            for (int si = 0; si < 8; si++)
#pragma unroll
                for (int li = 0; li < 8; li++) acc[si][li] += cl[li] * bs[si];
        }
        __syncthreads();
    }
    float* out = g_cbt + (size_t)(c * NG + g) * CSZ * CSZ;
#pragma unroll
    for (int si = 0; si < 8; si++) {
        int s = ty * 8 + si;
        *(float4*)(out + (size_t)s * CSZ + tx * 8)     = make_float4(acc[si][0], acc[si][1], acc[si][2], acc[si][3]);
        *(float4*)(out + (size_t)s * CSZ + tx * 8 + 4) = make_float4(acc[si][4], acc[si][5], acc[si][6], acc[si][7]);
    }
}

// ---------------- Y_diag + D residual ----------------
__global__ __launch_bounds__(256) void ydiag_kernel(const float* __restrict__ Dparam)
{
    int c = blockIdx.x, h = blockIdx.y, g = h >> 4;
    int tid = threadIdx.x, tx = tid & 15, ty = tid >> 4;
    __shared__ float xs[CSZ][DP];
    __shared__ float Ms[CSZ][17];
    __shared__ float acsS[CSZ];
    __shared__ float dts[CSZ];

    for (int i = tid; i < CSZ * DP / 4; i += 256) {
        int r = i >> 4, q = i & 15;
        *(float4*)&xs[r][q * 4] =
            *(const float4*)(g_xbc + (size_t)(c * CSZ + r) * DCONV + h * DP + q * 4);
    }
    if (tid < CSZ) {
        dts[tid]  = g_dt[(c * CSZ + tid) * NH + h];
        acsS[tid] = g_acs[(c * NH + h) * CSZ + tid];
    }
    __syncthreads();

    float acc[8][4];
#pragma unroll
    for (int i = 0; i < 8; i++)
#pragma unroll
        for (int j = 0; j < 4; j++) acc[i][j] = 0.f;

    const float* cbBase = g_cbt + (size_t)(c * NG + g) * CSZ * CSZ;
    const int ss_row = tid >> 4;
    const int lg     = tid & 15;

    for (int s0 = 0; s0 < CSZ; s0 += 16) {
        {
            const int s = s0 + ss_row;
            const float as  = acsS[s];
            const float dsv = dts[s];
            const float* cbRow = cbBase + (size_t)s * CSZ;
#pragma unroll
            for (int k = 0; k < 8; k++) {
                const int l = lg * 8 + k;
                float f = 0.f;
                if (s <= l) f = cbRow[l] * __expf(acsS[l] - as) * dsv;
                Ms[l][ss_row] = f;
            }
        }
        __syncthreads();

#pragma unroll
        for (int ss = 0; ss < 16; ss++) {
            const int s = s0 + ss;
            float msv[8];
#pragma unroll
            for (int i = 0; i < 8; i++) msv[i] = Ms[ty * 8 + i][ss];
            float4 xv4 = *(const float4*)&xs[s][tx * 4];
#pragma unroll
            for (int i = 0; i < 8; i++) {
                acc[i][0] += msv[i] * xv4.x;
                acc[i][1] += msv[i] * xv4.y;
                acc[i][2] += msv[i] * xv4.z;
                acc[i][3] += msv[i] * xv4.w;
            }
        }
        __syncthreads();
    }

    const float dcoef = Dparam[h];
#pragma unroll
    for (int i = 0; i < 8; i++) {
        int l = ty * 8 + i;
        float4 xr = *(const float4*)&xs[l][tx * 4];
        float4 o = make_float4(acc[i][0] + dcoef * xr.x, acc[i][1] + dcoef * xr.y,
                               acc[i][2] + dcoef * xr.z, acc[i][3] + dcoef * xr.w);
        *(float4*)(g_y + (size_t)(c * CSZ + l) * DINTER + h * DP + tx * 4) = o;
    }
}

// ---------------- Local chunk states ----------------
__global__ __launch_bounds__(256) void states_kernel()
{
    int c = blockIdx.x, h = blockIdx.y, g = h >> 4;
    int tid = threadIdx.x, tx = tid & 15, ty = tid >> 4;
    __shared__ float Bsh[32][DN];
    __shared__ float xds[32][DP];
    __shared__ float dec[32];
    float acc[4][8];
#pragma unroll
    for (int i = 0; i < 4; i++)
#pragma unroll
        for (int j = 0; j < 8; j++) acc[i][j] = 0.f;

    const float al = g_alast[c * NH + h];
    for (int l0 = 0; l0 < CSZ; l0 += 32) {
        for (int i = tid; i < 32 * DN / 4; i += 256) {
            int r = i >> 5, q = i & 31;
            *(float4*)&Bsh[r][q * 4] = *(const float4*)(
                g_xbc + (size_t)(c * CSZ + l0 + r) * DCONV + DINTER + g * DN + q * 4);
        }
        for (int i = tid; i < 32 * DP / 4; i += 256) {
            int r = i >> 4, q = i & 15;
            int t = c * CSZ + l0 + r;
            float4 xv = *(const float4*)(g_xbc + (size_t)t * DCONV + h * DP + q * 4);
            float d = g_dt[t * NH + h];
            xv.x *= d; xv.y *= d; xv.z *= d; xv.w *= d;
            *(float4*)&xds[r][q * 4] = xv;
        }
        if (tid < 32) dec[tid] = __expf(al - g_acs[(c * NH + h) * CSZ + l0 + tid]);
        __syncthreads();
#pragma unroll 8
        for (int ll = 0; ll < 32; ll++) {
            float d = dec[ll];
            float4 b0 = *(const float4*)&Bsh[ll][tx * 8];
            float4 b1 = *(const float4*)&Bsh[ll][tx * 8 + 4];
            float bb[8] = {b0.x, b0.y, b0.z, b0.w, b1.x, b1.y, b1.z, b1.w};
            float4 xv = *(const float4*)&xds[ll][ty * 4];
            float xp[4] = {xv.x * d, xv.y * d, xv.z * d, xv.w * d};
#pragma unroll
            for (int pi = 0; pi < 4; pi++)
#pragma unroll
                for (int nj = 0; nj < 8; nj++) acc[pi][nj] += xp[pi] * bb[nj];
        }
        __syncthreads();
    }
    float* out = g_states + (size_t)(c * NH + h) * DP * DN;
#pragma unroll
    for (int pi = 0; pi < 4; pi++) {
        int p = ty * 4 + pi;
        *(float4*)(out + (size_t)p * DN + tx * 8)     = make_float4(acc[pi][0], acc[pi][1], acc[pi][2], acc[pi][3]);
        *(float4*)(out + (size_t)p * DN + tx * 8 + 4) = make_float4(acc[pi][4], acc[pi][5], acc[pi][6], acc[pi][7]);
    }
}

// ---------------- Inter-chunk scan ----------------
__global__ void prefix_kernel()
{
    int idx = blockIdx.x * blockDim.x + threadIdx.x;
    if (idx >= NH * DP * DN) return;
    int h = idx >> 13;
    float s = 0.f;
#pragma unroll
    for (int c = 0; c < NCH; c++) {
        size_t off = (size_t)c * NH * DP * DN + idx;
        g_prefix[off] = s;
        s = __expf(g_alast[c * NH + h]) * s + g_states[off];
    }
}

// ---------------- Y_off ----------------
__global__ __launch_bounds__(256) void yoff_kernel()
{
    int c = blockIdx.x, h = blockIdx.y, g = h >> 4;
    int tid = threadIdx.x, tx = tid & 15, ty = tid >> 4;
    __shared__ float Cs[CSZ][32];
    __shared__ float Pf[DP][33];
    __shared__ float acsS[CSZ];
    if (tid < CSZ) acsS[tid] = g_acs[(c * NH + h) * CSZ + tid];

    float acc[8][4];
#pragma unroll
    for (int i = 0; i < 8; i++)
#pragma unroll
        for (int j = 0; j < 4; j++) acc[i][j] = 0.f;

    for (int n0 = 0; n0 < DN; n0 += 32) {
        for (int i = tid; i < CSZ * 8; i += 256) {
            int r = i >> 3, q = i & 7;
            *(float4*)&Cs[r][q * 4] = *(const float4*)(
                g_xbc + (size_t)(c * CSZ + r) * DCONV + DINTER + NG * DN + g * DN + n0 + q * 4);
        }
        for (int i = tid; i < DP * 8; i += 256) {
            int r = i >> 3, q = i & 7;
            float4 v = *(const float4*)(
                g_prefix + ((size_t)(c * NH + h) * DP + r) * DN + n0 + q * 4);
            Pf[r][q * 4 + 0] = v.x; Pf[r][q * 4 + 1] = v.y;
            Pf[r][q * 4 + 2] = v.z; Pf[r][q * 4 + 3] = v.w;
        }
        __syncthreads();
#pragma unroll 8
        for (int nn = 0; nn < 32; nn++) {
            float cl[8], pv[4];
#pragma unroll
            for (int i = 0; i < 8; i++) cl[i] = Cs[ty * 8 + i][nn];
#pragma unroll
            for (int j = 0; j < 4; j++) pv[j] = Pf[tx * 4 + j][nn];
#pragma unroll
            for (int i = 0; i < 8; i++)
#pragma unroll
                for (int j = 0; j < 4; j++) acc[i][j] += cl[i] * pv[j];
        }
        __syncthreads();
    }
#pragma unroll
    for (int i = 0; i < 8; i++) {
        int l = ty * 8 + i;
        float e = __expf(acsS[l]);
        float* yp = g_y + (size_t)(c * CSZ + l) * DINTER + h * DP + tx * 4;
        float4 y = *(float4*)yp;
        y.x += e * acc[i][0]; y.y += e * acc[i][1];
        y.z += e * acc[i][2]; y.w += e * acc[i][3];
        *(float4*)yp = y;
    }
}

// ---------------- RMSNorm * norm_w * silu(gate); output tf32-rounded ----------------
__global__ __launch_bounds__(256) void rms_gate_kernel(const float* __restrict__ norm_w)
{
    int t = blockIdx.x, tid = threadIdx.x;
    const size_t base = (size_t)t * DINTER;
    float ss = 0.f;
    for (int i = tid; i < DINTER; i += 256) {
        float v = g_y[base + i];
        ss += v * v;
    }
    __shared__ float red[256];
    red[tid] = ss;
    __syncthreads();
#pragma unroll
    for (int o = 128; o > 0; o >>= 1) {
        if (tid < o) red[tid] += red[tid + o];
        __syncthreads();
    }
    float inv = rsqrtf(red[0] / (float)DINTER + RMS_EPS);
    for (int i = tid; i < DINTER; i += 256) {
        float v = g_y[base + i] * inv * norm_w[i];
        v *= fast_silu(g_proj[(size_t)t * DPROJ + i]);
        ((uint32_t*)g_y)[base + i] = f2tf32(v);
    }
}

// ---------------- Launch ----------------
extern "C" void kernel_launch(void* const* d_in, const int* in_sizes, int n_in,
                              void* d_out, int out_size)
{
    (void)in_sizes; (void)n_in; (void)out_size;
    const float* hs         = (const float*)d_in[0];
    const float* in_proj_w  = (const float*)d_in[1];
    const float* conv_w     = (const float*)d_in[2];
    const float* conv_b     = (const float*)d_in[3];
    const float* dt_bias    = (const float*)d_in[4];
    const float* A_log      = (const float*)d_in[5];
    const float* Dp         = (const float*)d_in[6];
    const float* norm_w     = (const float*)d_in[7];
    const float* out_proj_w = (const float*)d_in[8];
    float* out = (float*)d_out;

    void *p_proj = nullptr, *p_y = nullptr, *p_hst = nullptr, *p_w1t = nullptr, *p_w2t = nullptr;
    cudaGetSymbolAddress(&p_proj, g_proj);
    cudaGetSymbolAddress(&p_y, g_y);
    cudaGetSymbolAddress(&p_hst, g_hst);
    cudaGetSymbolAddress(&p_w1t, g_w1t);
    cudaGetSymbolAddress(&p_w2t, g_w2t);

    cudaFuncSetAttribute(gemm_tf32_kernel, cudaFuncAttributeMaxDynamicSharedMemorySize, GEMM_DSMEM);

    // 0) pre-convert GEMM operands to tf32 bits
    {
        int n4;
        n4 = LSEQ * DMODEL / 4;
        cvt_tf32_kernel<<<(n4 + 255) / 256, 256>>>(hs, (float*)p_hst, n4);
        n4 = DPROJ * DMODEL / 4;
        cvt_tf32_kernel<<<(n4 + 255) / 256, 256>>>(in_proj_w, (float*)p_w1t, n4);
        n4 = DMODEL * DINTER / 4;
        cvt_tf32_kernel<<<(n4 + 255) / 256, 256>>>(out_proj_w, (float*)p_w2t, n4);
    }

    // 1) in-proj GEMM
    gemm_tf32_kernel<<<dim3(DPROJ / 128, LSEQ / 128), 256, GEMM_DSMEM>>>(
        (const float*)p_hst, (const float*)p_w1t, (float*)p_proj, DPROJ, DMODEL);
    // 2) causal depthwise conv + silu
    conv_silu_kernel<<<(LSEQ * DCONV + 255) / 256, 256>>>(conv_w, conv_b);
    // 3) dt softplus + per-chunk cumsum of A*dt
    dt_scan_kernel<<<dim3(NCH, NH), CSZ>>>(dt_bias, A_log);
    // 4) C·B^T per (chunk, group)
    cb_kernel<<<dim3(NCH, NG), 256>>>();
    // 5) intra-chunk output + D residual
    ydiag_kernel<<<dim3(NCH, NH), 256>>>(Dp);
    // 6) local chunk states
    states_kernel<<<dim3(NCH, NH), 256>>>();
    // 7) inter-chunk state scan
    prefix_kernel<<<(NH * DP * DN + 255) / 256, 256>>>();
    // 8) off-diagonal output
    yoff_kernel<<<dim3(NCH, NH), 256>>>();
    // 9) gated RMSNorm (writes tf32-rounded)
    rms_gate_kernel<<<LSEQ, 256>>>(norm_w);
    // 10) out-proj GEMM
    gemm_tf32_kernel<<<dim3(DMODEL / 128, LSEQ / 128), 256, GEMM_DSMEM>>>(
        (const float*)p_y, (const float*)p_w2t, out, DMODEL, DINTER);
}

// round 9
// speedup vs baseline: 1.3273x; 1.0684x over previous
#include <cuda_runtime.h>
#include <math.h>
#include <stdint.h>

// ---------------- Problem constants ----------------
#define LSEQ   2048
#define DMODEL 4096
#define NH     128
#define DP     64
#define NG     8
#define DN     128
#define CSZ    128
#define NCH    (LSEQ / CSZ)
#define KCONV  4
#define DINTER 8192
#define DCONV  10240
#define DPROJ  18560
#define RMS_EPS 1e-5f

// ---------------- Scratch ----------------
__device__ float g_proj[LSEQ * DPROJ];
__device__ float g_xbc[LSEQ * DCONV];
__device__ float g_dt[LSEQ * NH];
__device__ float g_acs[NCH * NH * CSZ];
__device__ float g_alast[NCH * NH];
__device__ float g_cbt[NCH * NG * CSZ * CSZ];
__device__ float g_states[NCH * NH * DP * DN];
__device__ float g_prefix[NCH * NH * DP * DN];
__device__ float g_y[LSEQ * DINTER];
__device__ float g_hst[LSEQ * DMODEL];
__device__ float g_w1t[DPROJ * DMODEL];
__device__ float g_w2t[DMODEL * DINTER];

// ---------------- helpers ----------------
__device__ __forceinline__ uint32_t f2tf32(float f) {
    uint32_t r;
    asm("cvt.rna.tf32.f32 %0, %1;" : "=r"(r) : "f"(f));
    return r;
}
__device__ __forceinline__ void mma_tf32(float c[4], const uint32_t a[4], const uint32_t b[2]) {
    asm volatile(
        "mma.sync.aligned.m16n8k8.row.col.f32.tf32.tf32.f32 "
        "{%0,%1,%2,%3}, {%4,%5,%6,%7}, {%8,%9}, {%0,%1,%2,%3};"
        : "+f"(c[0]), "+f"(c[1]), "+f"(c[2]), "+f"(c[3])
        : "r"(a[0]), "r"(a[1]), "r"(a[2]), "r"(a[3]), "r"(b[0]), "r"(b[1]));
}
__device__ __forceinline__ float fast_silu(float x) {
    float t;
    asm("tanh.approx.f32 %0, %1;" : "=f"(t) : "f"(x * 0.5f));
    return 0.5f * x * (1.f + t);
}
__device__ __forceinline__ uint32_t smem_u32(const void* p) {
    uint32_t a;
    asm("{ .reg .u64 t; cvta.to.shared.u64 t, %1; cvt.u32.u64 %0, t; }" : "=r"(a) : "l"(p));
    return a;
}
__device__ __forceinline__ void cp_async16(uint32_t saddr, const void* gaddr) {
    asm volatile("cp.async.cg.shared.global [%0], [%1], 16;" :: "r"(saddr), "l"(gaddr));
}
#define CP_COMMIT() asm volatile("cp.async.commit_group;" ::: "memory")
#define CP_WAIT(n)  asm volatile("cp.async.wait_group %0;" :: "n"(n) : "memory")

// ---------------- tf32 pre-conversion ----------------
__global__ void cvt_tf32_kernel(const float* __restrict__ in, float* __restrict__ out, int n4)
{
    int i = blockIdx.x * blockDim.x + threadIdx.x;
    if (i >= n4) return;
    float4 v = ((const float4*)in)[i];
    uint4 o;
    o.x = f2tf32(v.x); o.y = f2tf32(v.y); o.z = f2tf32(v.z); o.w = f2tf32(v.w);
    ((uint4*)out)[i] = o;
}

// ---------------- tf32 GEMM: 128 threads, warp tile 64x64, BK=32, 3 stages ----------------
// C[M,Nd] = A[M,Kd]*B[Nd,Kd]^T. BM=BN=128. 4 warps in 2x2 grid (wm/wn 64 each).
// Smem: 128 rows x 32 words/operand/stage, 16B chunk at (c ^ (row&7)).
#define GSTAGES 3
#define STAGEW  (128 * 32)
#define GEMM_DSMEM (GSTAGES * 2 * STAGEW * 4)   // 98304 bytes

__global__ __launch_bounds__(128, 2) void gemm_tf32_kernel(
    const float* __restrict__ A, const float* __restrict__ B, float* __restrict__ C,
    int Nd, int Kd)
{
    extern __shared__ float smf[];
    float* const Abuf = smf;
    float* const Bbuf = smf + GSTAGES * STAGEW;

    const int tid  = threadIdx.x;
    const int lane = tid & 31, warp = tid >> 5;
    const int wm = (warp >> 1) * 64;
    const int wn = (warp & 1) * 64;
    const int g  = lane >> 2, tq = lane & 3;
    const int bm = blockIdx.y * 128, bn = blockIdx.x * 128;

    // staging: thread handles rows r0+16j (j=0..7), 16B chunk c within row
    const int r0 = tid >> 3, c = tid & 7;
    const uint32_t swoff = (uint32_t)((c ^ (r0 & 7)) << 4);
    const float* AgBase = A + (size_t)(bm + r0) * Kd + c * 4;
    const float* BgBase = B + (size_t)(bn + r0) * Kd + c * 4;
    const uint32_t sA0 = smem_u32(Abuf) + (uint32_t)(r0 * 128) + swoff;
    const uint32_t sB0 = smem_u32(Bbuf) + (uint32_t)(r0 * 128) + swoff;

    const int KT = Kd >> 5;

#pragma unroll
    for (int s = 0; s < GSTAGES - 1; s++) {
        const uint32_t so = (uint32_t)(s * STAGEW * 4);
        const size_t ko = (size_t)s * 32;
#pragma unroll
        for (int j = 0; j < 8; j++) {
            cp_async16(sA0 + so + j * 16 * 128, AgBase + (size_t)(16 * j) * Kd + ko);
            cp_async16(sB0 + so + j * 16 * 128, BgBase + (size_t)(16 * j) * Kd + ko);
        }
        CP_COMMIT();
    }

    float acc[4][8][4];
#pragma unroll
    for (int mt = 0; mt < 4; mt++)
#pragma unroll
        for (int nt = 0; nt < 8; nt++)
#pragma unroll
            for (int qq = 0; qq < 4; qq++) acc[mt][nt][qq] = 0.f;

    int buf = 0;
    for (int kt = 0; kt < KT; kt++) {
        CP_WAIT(1);
        __syncthreads();

        const int pf = kt + GSTAGES - 1;
        if (pf < KT) {
            const int pb = pf % GSTAGES;
            const uint32_t so = (uint32_t)(pb * STAGEW * 4);
            const size_t ko = (size_t)pf * 32;
#pragma unroll
            for (int j = 0; j < 8; j++) {
                cp_async16(sA0 + so + j * 16 * 128, AgBase + (size_t)(16 * j) * Kd + ko);
                cp_async16(sB0 + so + j * 16 * 128, BgBase + (size_t)(16 * j) * Kd + ko);
            }
        }
        CP_COMMIT();

        const uint32_t* As = (const uint32_t*)(Abuf + buf * STAGEW);
        const uint32_t* Bs = (const uint32_t*)(Bbuf + buf * STAGEW);
#pragma unroll
        for (int ks = 0; ks < 4; ks++) {
            const int kq0 = ((2 * ks)     ^ g) * 4 + tq;
            const int kq1 = ((2 * ks + 1) ^ g) * 4 + tq;
            uint32_t af[4][4], bf[8][2];
#pragma unroll
            for (int mt = 0; mt < 4; mt++) {
                const int m0 = wm + mt * 16;
                af[mt][0] = As[(m0 + g    ) * 32 + kq0];
                af[mt][1] = As[(m0 + g + 8) * 32 + kq0];
                af[mt][2] = As[(m0 + g    ) * 32 + kq1];
                af[mt][3] = As[(m0 + g + 8) * 32 + kq1];
            }
#pragma unroll
            for (int nt = 0; nt < 8; nt++) {
                const int n0 = wn + nt * 8;
                bf[nt][0] = Bs[(n0 + g) * 32 + kq0];
                bf[nt][1] = Bs[(n0 + g) * 32 + kq1];
            }
#pragma unroll
            for (int mt = 0; mt < 4; mt++)
#pragma unroll
                for (int nt = 0; nt < 8; nt++)
                    mma_tf32(acc[mt][nt], af[mt], bf[nt]);
        }
        buf = (buf + 1) % GSTAGES;
    }

#pragma unroll
    for (int mt = 0; mt < 4; mt++) {
#pragma unroll
        for (int nt = 0; nt < 8; nt++) {
            const int row = bm + wm + mt * 16 + g;
            const int col = bn + wn + nt * 8 + 2 * tq;
            *(float2*)&C[(size_t)row * Nd + col]       = make_float2(acc[mt][nt][0], acc[mt][nt][1]);
            *(float2*)&C[(size_t)(row + 8) * Nd + col] = make_float2(acc[mt][nt][2], acc[mt][nt][3]);
        }
    }
}

// ---------------- Depthwise causal conv (K=4) + SiLU ----------------
__global__ void conv_silu_kernel(const float* __restrict__ conv_w, const float* __restrict__ conv_b)
{
    int idx = blockIdx.x * blockDim.x + threadIdx.x;
    if (idx >= LSEQ * DCONV) return;
    int t = idx / DCONV, c = idx % DCONV;
    float acc = conv_b[c];
    const float* w = conv_w + c * KCONV;
#pragma unroll
    for (int k = 0; k < KCONV; k++) {
        int tt = t + k - (KCONV - 1);
        if (tt >= 0) acc += w[k] * g_proj[(size_t)tt * DPROJ + DINTER + c];
    }
    g_xbc[idx] = fast_silu(acc);
}

// ---------------- dt softplus + per-chunk cumsum of A*dt ----------------
__global__ __launch_bounds__(CSZ) void dt_scan_kernel(
    const float* __restrict__ dt_bias, const float* __restrict__ A_log)
{
    int c = blockIdx.x, h = blockIdx.y, l = threadIdx.x;
    int t = c * CSZ + l;
    float raw = g_proj[(size_t)t * DPROJ + DINTER + DCONV + h] + dt_bias[h];
    float dtp = (raw > 0.f) ? (raw + log1pf(__expf(-raw))) : log1pf(__expf(raw));
    g_dt[t * NH + h] = dtp;
    float a = -__expf(A_log[h]) * dtp;

    __shared__ float s[CSZ];
    s[l] = a;
    __syncthreads();
#pragma unroll
    for (int off = 1; off < CSZ; off <<= 1) {
        float v = (l >= off) ? s[l - off] : 0.f;
        __syncthreads();
        s[l] += v;
        __syncthreads();
    }
    g_acs[(c * NH + h) * CSZ + l] = s[l];
    if (l == CSZ - 1) g_alast[c * NH + h] = s[l];
}

// ---------------- CBt[c][g][s][l] = sum_n C[l,n]*B[s,n] ----------------
__global__ __launch_bounds__(256) void cb_kernel()
{
    int c = blockIdx.x, g = blockIdx.y;
    int tid = threadIdx.x, tx = tid & 15, ty = tid >> 4;
    __shared__ float Csn[16][CSZ];
    __shared__ float Bsn[16][CSZ];
    float acc[8][8];
#pragma unroll
    for (int i = 0; i < 8; i++)
#pragma unroll
        for (int j = 0; j < 8; j++) acc[i][j] = 0.f;

    const float* Cg = g_xbc + DINTER + NG * DN + g * DN;
    const float* Bg = g_xbc + DINTER + g * DN;

    for (int n0 = 0; n0 < DN; n0 += 16) {
        for (int i = tid; i < CSZ * 4; i += 256) {
            int r = i >> 2, q = i & 3;
            const size_t row = (size_t)(c * CSZ + r) * DCONV + n0 + q * 4;
            float4 cv = *(const float4*)(Cg + row);
            float4 bv = *(const float4*)(Bg + row);
            Csn[q * 4 + 0][r] = cv.x; Csn[q * 4 + 1][r] = cv.y;
            Csn[q * 4 + 2][r] = cv.z; Csn[q * 4 + 3][r] = cv.w;
            Bsn[q * 4 + 0][r] = bv.x; Bsn[q * 4 + 1][r] = bv.y;
            Bsn[q * 4 + 2][r] = bv.z; Bsn[q * 4 + 3][r] = bv.w;
        }
        __syncthreads();
#pragma unroll
        for (int nn = 0; nn < 16; nn++) {
            float4 c0 = *(const float4*)&Csn[nn][tx * 8];
            float4 c1 = *(const float4*)&Csn[nn][tx * 8 + 4];
            float4 b0 = *(const float4*)&Bsn[nn][ty * 8];
            float4 b1 = *(const float4*)&Bsn[nn][ty * 8 + 4];
            float cl[8] = {c0.x, c0.y, c0.z, c0.w, c1.x, c1.y, c1.z, c1.w};
            float bs[8] = {b0.x, b0.y, b0.z, b0.w, b1.x, b1.y, b1.z, b1.w};
#pragma unroll
            for (int si = 0; si < 8; si++)
#pragma unroll
                for (int li = 0; li < 8; li++) acc[si][li] += cl[li] * bs[si];
        }
        __syncthreads();
    }
    float* out = g_cbt + (size_t)(c * NG + g) * CSZ * CSZ;
#pragma unroll
    for (int si = 0; si < 8; si++) {
        int s = ty * 8 + si;
        *(float4*)(out + (size_t)s * CSZ + tx * 8)     = make_float4(acc[si][0], acc[si][1], acc[si][2], acc[si][3]);
        *(float4*)(out + (size_t)s * CSZ + tx * 8 + 4) = make_float4(acc[si][4], acc[si][5], acc[si][6], acc[si][7]);
    }
}

// ---------------- Y_diag + D residual ----------------
__global__ __launch_bounds__(256) void ydiag_kernel(const float* __restrict__ Dparam)
{
    int c = blockIdx.x, h = blockIdx.y, g = h >> 4;
    int tid = threadIdx.x, tx = tid & 15, ty = tid >> 4;
    __shared__ float xs[CSZ][DP];
    __shared__ float Ms[CSZ][17];
    __shared__ float acsS[CSZ];
    __shared__ float dts[CSZ];

    for (int i = tid; i < CSZ * DP / 4; i += 256) {
        int r = i >> 4, q = i & 15;
        *(float4*)&xs[r][q * 4] =
            *(const float4*)(g_xbc + (size_t)(c * CSZ + r) * DCONV + h * DP + q * 4);
    }
    if (tid < CSZ) {
        dts[tid]  = g_dt[(c * CSZ + tid) * NH + h];
        acsS[tid] = g_acs[(c * NH + h) * CSZ + tid];
    }
    __syncthreads();

    float acc[8][4];
#pragma unroll
    for (int i = 0; i < 8; i++)
#pragma unroll
        for (int j = 0; j < 4; j++) acc[i][j] = 0.f;

    const float* cbBase = g_cbt + (size_t)(c * NG + g) * CSZ * CSZ;
    const int ss_row = tid >> 4;
    const int lg     = tid & 15;

    for (int s0 = 0; s0 < CSZ; s0 += 16) {
        {
            const int s = s0 + ss_row;
            const float as  = acsS[s];
            const float dsv = dts[s];
            const float* cbRow = cbBase + (size_t)s * CSZ;
#pragma unroll
            for (int k = 0; k < 8; k++) {
                const int l = lg * 8 + k;
                float f = 0.f;
                if (s <= l) f = cbRow[l] * __expf(acsS[l] - as) * dsv;
                Ms[l][ss_row] = f;
            }
        }
        __syncthreads();

#pragma unroll
        for (int ss = 0; ss < 16; ss++) {
            const int s = s0 + ss;
            float msv[8];
#pragma unroll
            for (int i = 0; i < 8; i++) msv[i] = Ms[ty * 8 + i][ss];
            float4 xv4 = *(const float4*)&xs[s][tx * 4];
#pragma unroll
            for (int i = 0; i < 8; i++) {
                acc[i][0] += msv[i] * xv4.x;
                acc[i][1] += msv[i] * xv4.y;
                acc[i][2] += msv[i] * xv4.z;
                acc[i][3] += msv[i] * xv4.w;
            }
        }
        __syncthreads();
    }

    const float dcoef = Dparam[h];
#pragma unroll
    for (int i = 0; i < 8; i++) {
        int l = ty * 8 + i;
        float4 xr = *(const float4*)&xs[l][tx * 4];
        float4 o = make_float4(acc[i][0] + dcoef * xr.x, acc[i][1] + dcoef * xr.y,
                               acc[i][2] + dcoef * xr.z, acc[i][3] + dcoef * xr.w);
        *(float4*)(g_y + (size_t)(c * CSZ + l) * DINTER + h * DP + tx * 4) = o;
    }
}

// ---------------- Local chunk states ----------------
__global__ __launch_bounds__(256) void states_kernel()
{
    int c = blockIdx.x, h = blockIdx.y, g = h >> 4;
    int tid = threadIdx.x, tx = tid & 15, ty = tid >> 4;
    __shared__ float Bsh[32][DN];
    __shared__ float xds[32][DP];
    __shared__ float dec[32];
    float acc[4][8];
#pragma unroll
    for (int i = 0; i < 4; i++)
#pragma unroll
        for (int j = 0; j < 8; j++) acc[i][j] = 0.f;

    const float al = g_alast[c * NH + h];
    for (int l0 = 0; l0 < CSZ; l0 += 32) {
        for (int i = tid; i < 32 * DN / 4; i += 256) {
            int r = i >> 5, q = i & 31;
            *(float4*)&Bsh[r][q * 4] = *(const float4*)(
                g_xbc + (size_t)(c * CSZ + l0 + r) * DCONV + DINTER + g * DN + q * 4);
        }
        for (int i = tid; i < 32 * DP / 4; i += 256) {
            int r = i >> 4, q = i & 15;
            int t = c * CSZ + l0 + r;
            float4 xv = *(const float4*)(g_xbc + (size_t)t * DCONV + h * DP + q * 4);
            float d = g_dt[t * NH + h];
            xv.x *= d; xv.y *= d; xv.z *= d; xv.w *= d;
            *(float4*)&xds[r][q * 4] = xv;
        }
        if (tid < 32) dec[tid] = __expf(al - g_acs[(c * NH + h) * CSZ + l0 + tid]);
        __syncthreads();
#pragma unroll 8
        for (int ll = 0; ll < 32; ll++) {
            float d = dec[ll];
            float4 b0 = *(const float4*)&Bsh[ll][tx * 8];
            float4 b1 = *(const float4*)&Bsh[ll][tx * 8 + 4];
            float bb[8] = {b0.x, b0.y, b0.z, b0.w, b1.x, b1.y, b1.z, b1.w};
            float4 xv = *(const float4*)&xds[ll][ty * 4];
            float xp[4] = {xv.x * d, xv.y * d, xv.z * d, xv.w * d};
#pragma unroll
            for (int pi = 0; pi < 4; pi++)
#pragma unroll
                for (int nj = 0; nj < 8; nj++) acc[pi][nj] += xp[pi] * bb[nj];
        }
        __syncthreads();
    }
    float* out = g_states + (size_t)(c * NH + h) * DP * DN;
#pragma unroll
    for (int pi = 0; pi < 4; pi++) {
        int p = ty * 4 + pi;
        *(float4*)(out + (size_t)p * DN + tx * 8)     = make_float4(acc[pi][0], acc[pi][1], acc[pi][2], acc[pi][3]);
        *(float4*)(out + (size_t)p * DN + tx * 8 + 4) = make_float4(acc[pi][4], acc[pi][5], acc[pi][6], acc[pi][7]);
    }
}

// ---------------- Inter-chunk scan ----------------
__global__ void prefix_kernel()
{
    int idx = blockIdx.x * blockDim.x + threadIdx.x;
    if (idx >= NH * DP * DN) return;
    int h = idx >> 13;
    float s = 0.f;
#pragma unroll
    for (int c = 0; c < NCH; c++) {
        size_t off = (size_t)c * NH * DP * DN + idx;
        g_prefix[off] = s;
        s = __expf(g_alast[c * NH + h]) * s + g_states[off];
    }
}

// ---------------- Y_off ----------------
__global__ __launch_bounds__(256) void yoff_kernel()
{
    int c = blockIdx.x, h = blockIdx.y, g = h >> 4;
    int tid = threadIdx.x, tx = tid & 15, ty = tid >> 4;
    __shared__ float Cs[CSZ][32];
    __shared__ float Pf[DP][33];
    __shared__ float acsS[CSZ];
    if (tid < CSZ) acsS[tid] = g_acs[(c * NH + h) * CSZ + tid];

    float acc[8][4];
#pragma unroll
    for (int i = 0; i < 8; i++)
#pragma unroll
        for (int j = 0; j < 4; j++) acc[i][j] = 0.f;

    for (int n0 = 0; n0 < DN; n0 += 32) {
        for (int i = tid; i < CSZ * 8; i += 256) {
            int r = i >> 3, q = i & 7;
            *(float4*)&Cs[r][q * 4] = *(const float4*)(
                g_xbc + (size_t)(c * CSZ + r) * DCONV + DINTER + NG * DN + g * DN + n0 + q * 4);
        }
        for (int i = tid; i < DP * 8; i += 256) {
            int r = i >> 3, q = i & 7;
            float4 v = *(const float4*)(
                g_prefix + ((size_t)(c * NH + h) * DP + r) * DN + n0 + q * 4);
            Pf[r][q * 4 + 0] = v.x; Pf[r][q * 4 + 1] = v.y;
            Pf[r][q * 4 + 2] = v.z; Pf[r][q * 4 + 3] = v.w;
        }
        __syncthreads();
#pragma unroll 8
        for (int nn = 0; nn < 32; nn++) {
            float cl[8], pv[4];
#pragma unroll
            for (int i = 0; i < 8; i++) cl[i] = Cs[ty * 8 + i][nn];
#pragma unroll
            for (int j = 0; j < 4; j++) pv[j] = Pf[tx * 4 + j][nn];
#pragma unroll
            for (int i = 0; i < 8; i++)
#pragma unroll
                for (int j = 0; j < 4; j++) acc[i][j] += cl[i] * pv[j];
        }
        __syncthreads();
    }
#pragma unroll
    for (int i = 0; i < 8; i++) {
        int l = ty * 8 + i;
        float e = __expf(acsS[l]);
        float* yp = g_y + (size_t)(c * CSZ + l) * DINTER + h * DP + tx * 4;
        float4 y = *(float4*)yp;
        y.x += e * acc[i][0]; y.y += e * acc[i][1];
        y.z += e * acc[i][2]; y.w += e * acc[i][3];
        *(float4*)yp = y;
    }
}

// ---------------- RMSNorm * norm_w * silu(gate); output tf32-rounded ----------------
__global__ __launch_bounds__(256) void rms_gate_kernel(const float* __restrict__ norm_w)
{
    int t = blockIdx.x, tid = threadIdx.x;
    const size_t base = (size_t)t * DINTER;
    float ss = 0.f;
    for (int i = tid; i < DINTER; i += 256) {
        float v = g_y[base + i];
        ss += v * v;
    }
    __shared__ float red[256];
    red[tid] = ss;
    __syncthreads();
#pragma unroll
    for (int o = 128; o > 0; o >>= 1) {
        if (tid < o) red[tid] += red[tid + o];
        __syncthreads();
    }
    float inv = rsqrtf(red[0] / (float)DINTER + RMS_EPS);
    for (int i = tid; i < DINTER; i += 256) {
        float v = g_y[base + i] * inv * norm_w[i];
        v *= fast_silu(g_proj[(size_t)t * DPROJ + i]);
        ((uint32_t*)g_y)[base + i] = f2tf32(v);
    }
}

// ---------------- Launch ----------------
extern "C" void kernel_launch(void* const* d_in, const int* in_sizes, int n_in,
                              void* d_out, int out_size)
{
    (void)in_sizes; (void)n_in; (void)out_size;
    const float* hs         = (const float*)d_in[0];
    const float* in_proj_w  = (const float*)d_in[1];
    const float* conv_w     = (const float*)d_in[2];
    const float* conv_b     = (const float*)d_in[3];
    const float* dt_bias    = (const float*)d_in[4];
    const float* A_log      = (const float*)d_in[5];
    const float* Dp         = (const float*)d_in[6];
    const float* norm_w     = (const float*)d_in[7];
    const float* out_proj_w = (const float*)d_in[8];
    float* out = (float*)d_out;

    void *p_proj = nullptr, *p_y = nullptr, *p_hst = nullptr, *p_w1t = nullptr, *p_w2t = nullptr;
    cudaGetSymbolAddress(&p_proj, g_proj);
    cudaGetSymbolAddress(&p_y, g_y);
    cudaGetSymbolAddress(&p_hst, g_hst);
    cudaGetSymbolAddress(&p_w1t, g_w1t);
    cudaGetSymbolAddress(&p_w2t, g_w2t);

    cudaFuncSetAttribute(gemm_tf32_kernel, cudaFuncAttributeMaxDynamicSharedMemorySize, GEMM_DSMEM);

    // 0) pre-convert GEMM operands to tf32 bits
    {
        int n4;
        n4 = LSEQ * DMODEL / 4;
        cvt_tf32_kernel<<<(n4 + 255) / 256, 256>>>(hs, (float*)p_hst, n4);
        n4 = DPROJ * DMODEL / 4;
        cvt_tf32_kernel<<<(n4 + 255) / 256, 256>>>(in_proj_w, (float*)p_w1t, n4);
        n4 = DMODEL * DINTER / 4;
        cvt_tf32_kernel<<<(n4 + 255) / 256, 256>>>(out_proj_w, (float*)p_w2t, n4);
    }

    // 1) in-proj GEMM
    gemm_tf32_kernel<<<dim3(DPROJ / 128, LSEQ / 128), 128, GEMM_DSMEM>>>(
        (const float*)p_hst, (const float*)p_w1t, (float*)p_proj, DPROJ, DMODEL);
    // 2) causal depthwise conv + silu
    conv_silu_kernel<<<(LSEQ * DCONV + 255) / 256, 256>>>(conv_w, conv_b);
    // 3) dt softplus + per-chunk cumsum of A*dt
    dt_scan_kernel<<<dim3(NCH, NH), CSZ>>>(dt_bias, A_log);
    // 4) C·B^T per (chunk, group)
    cb_kernel<<<dim3(NCH, NG), 256>>>();
    // 5) intra-chunk output + D residual
    ydiag_kernel<<<dim3(NCH, NH), 256>>>(Dp);
    // 6) local chunk states
    states_kernel<<<dim3(NCH, NH), 256>>>();
    // 7) inter-chunk state scan
    prefix_kernel<<<(NH * DP * DN + 255) / 256, 256>>>();
    // 8) off-diagonal output
    yoff_kernel<<<dim3(NCH, NH), 256>>>();
    // 9) gated RMSNorm (writes tf32-rounded)
    rms_gate_kernel<<<LSEQ, 256>>>(norm_w);
    // 10) out-proj GEMM
    gemm_tf32_kernel<<<dim3(DMODEL / 128, LSEQ / 128), 128, GEMM_DSMEM>>>(
        (const float*)p_y, (const float*)p_w2t, out, DMODEL, DINTER);
}

// round 10
// speedup vs baseline: 2.0949x; 1.5783x over previous
#include <cuda_runtime.h>
#include <cuda_fp16.h>
#include <math.h>
#include <stdint.h>

// ---------------- Problem constants ----------------
#define LSEQ   2048
#define DMODEL 4096
#define NH     128
#define DP     64
#define NG     8
#define DN     128
#define CSZ    128
#define NCH    (LSEQ / CSZ)
#define KCONV  4
#define DINTER 8192
#define DCONV  10240
#define DPROJ  18560
#define RMS_EPS 1e-5f

// ---------------- Scratch ----------------
__device__ float g_proj[LSEQ * DPROJ];
__device__ float g_xbc[LSEQ * DCONV];
__device__ float g_dt[LSEQ * NH];
__device__ float g_acs[NCH * NH * CSZ];
__device__ float g_alast[NCH * NH];
__device__ float g_cbt[NCH * NG * CSZ * CSZ];
__device__ float g_states[NCH * NH * DP * DN];
__device__ float g_prefix[NCH * NH * DP * DN];
__device__ float g_y[LSEQ * DINTER];
// fp16 copies of GEMM operands
__device__ __half g_hsth[LSEQ * DMODEL];
__device__ __half g_w1th[DPROJ * DMODEL];
__device__ __half g_w2th[DMODEL * DINTER];
__device__ __half g_yh[LSEQ * DINTER];

// ---------------- helpers ----------------
__device__ __forceinline__ void mma_f16(float c[4], const uint32_t a[4], const uint32_t b[2]) {
    asm volatile(
        "mma.sync.aligned.m16n8k16.row.col.f32.f16.f16.f32 "
        "{%0,%1,%2,%3}, {%4,%5,%6,%7}, {%8,%9}, {%0,%1,%2,%3};"
        : "+f"(c[0]), "+f"(c[1]), "+f"(c[2]), "+f"(c[3])
        : "r"(a[0]), "r"(a[1]), "r"(a[2]), "r"(a[3]), "r"(b[0]), "r"(b[1]));
}
__device__ __forceinline__ float fast_silu(float x) {
    float t;
    asm("tanh.approx.f32 %0, %1;" : "=f"(t) : "f"(x * 0.5f));
    return 0.5f * x * (1.f + t);
}
__device__ __forceinline__ uint32_t smem_u32(const void* p) {
    uint32_t a;
    asm("{ .reg .u64 t; cvta.to.shared.u64 t, %1; cvt.u32.u64 %0, t; }" : "=r"(a) : "l"(p));
    return a;
}
__device__ __forceinline__ void cp_async16(uint32_t saddr, const void* gaddr) {
    asm volatile("cp.async.cg.shared.global [%0], [%1], 16;" :: "r"(saddr), "l"(gaddr));
}
#define CP_COMMIT() asm volatile("cp.async.commit_group;" ::: "memory")
#define CP_WAIT(n)  asm volatile("cp.async.wait_group %0;" :: "n"(n) : "memory")

// ---------------- fp32 -> fp16 pre-conversion (float4 in, 8B out) ----------------
__global__ void cvt_f16_kernel(const float* __restrict__ in, __half* __restrict__ out, int n4)
{
    int i = blockIdx.x * blockDim.x + threadIdx.x;
    if (i >= n4) return;
    float4 v = ((const float4*)in)[i];
    __half2 h0 = __floats2half2_rn(v.x, v.y);
    __half2 h1 = __floats2half2_rn(v.z, v.w);
    uint2 o;
    o.x = *(uint32_t*)&h0;
    o.y = *(uint32_t*)&h1;
    ((uint2*)out)[i] = o;
}

// ---------------- fp16 GEMM: 128 threads, warp tile 64x64, BK=64, 3 stages ----------------
// C[M,Nd] = A[M,Kd]*B[Nd,Kd]^T (A,B fp16 row-major, C fp32). BM=BN=128.
// Smem stage: 128 rows x 128 bytes (64 halfs) per operand; 16B chunk c at (c ^ (row&7)).
#define GSTAGES 3
#define STAGEW  (128 * 32)                      // uint32 words per operand per stage
#define GEMM_DSMEM (GSTAGES * 2 * STAGEW * 4)   // 98304 bytes

__global__ __launch_bounds__(128, 2) void gemm_f16_kernel(
    const __half* __restrict__ A, const __half* __restrict__ B, float* __restrict__ C,
    int Nd, int Kd)
{
    extern __shared__ float smf[];
    float* const Abuf = smf;
    float* const Bbuf = smf + GSTAGES * STAGEW;

    const int tid  = threadIdx.x;
    const int lane = tid & 31, warp = tid >> 5;
    const int wm = (warp >> 1) * 64;
    const int wn = (warp & 1) * 64;
    const int g  = lane >> 2, tq = lane & 3;
    const int bm = blockIdx.y * 128, bn = blockIdx.x * 128;

    // staging: thread handles rows r0+16j (j=0..7), 16B chunk c (8 halfs) within row
    const int r0 = tid >> 3, c = tid & 7;
    const uint32_t swoff = (uint32_t)((c ^ (r0 & 7)) << 4);
    const __half* AgBase = A + (size_t)(bm + r0) * Kd + c * 8;
    const __half* BgBase = B + (size_t)(bn + r0) * Kd + c * 8;
    const uint32_t sA0 = smem_u32(Abuf) + (uint32_t)(r0 * 128) + swoff;
    const uint32_t sB0 = smem_u32(Bbuf) + (uint32_t)(r0 * 128) + swoff;

    const int KT = Kd >> 6;   // BK = 64 halfs

#pragma unroll
    for (int s = 0; s < GSTAGES - 1; s++) {
        const uint32_t so = (uint32_t)(s * STAGEW * 4);
        const size_t ko = (size_t)s * 64;
#pragma unroll
        for (int j = 0; j < 8; j++) {
            cp_async16(sA0 + so + j * 16 * 128, AgBase + (size_t)(16 * j) * Kd + ko);
            cp_async16(sB0 + so + j * 16 * 128, BgBase + (size_t)(16 * j) * Kd + ko);
        }
        CP_COMMIT();
    }

    float acc[4][8][4];
#pragma unroll
    for (int mt = 0; mt < 4; mt++)
#pragma unroll
        for (int nt = 0; nt < 8; nt++)
#pragma unroll
            for (int qq = 0; qq < 4; qq++) acc[mt][nt][qq] = 0.f;

    int buf = 0;
    for (int kt = 0; kt < KT; kt++) {
        CP_WAIT(1);
        __syncthreads();

        const int pf = kt + GSTAGES - 1;
        if (pf < KT) {
            const int pb = pf % GSTAGES;
            const uint32_t so = (uint32_t)(pb * STAGEW * 4);
            const size_t ko = (size_t)pf * 64;
#pragma unroll
            for (int j = 0; j < 8; j++) {
                cp_async16(sA0 + so + j * 16 * 128, AgBase + (size_t)(16 * j) * Kd + ko);
                cp_async16(sB0 + so + j * 16 * 128, BgBase + (size_t)(16 * j) * Kd + ko);
            }
        }
        CP_COMMIT();

        const uint32_t* As = (const uint32_t*)(Abuf + buf * STAGEW);
        const uint32_t* Bs = (const uint32_t*)(Bbuf + buf * STAGEW);
        // 4 k-steps of 16 halfs each; chunks 2ks, 2ks+1 within the 128B row
#pragma unroll
        for (int ks = 0; ks < 4; ks++) {
            const int kq0 = ((2 * ks)     ^ g) * 4 + tq;
            const int kq1 = ((2 * ks + 1) ^ g) * 4 + tq;
            uint32_t af[4][4], bf[8][2];
#pragma unroll
            for (int mt = 0; mt < 4; mt++) {
                const int m0 = wm + mt * 16;
                af[mt][0] = As[(m0 + g    ) * 32 + kq0];
                af[mt][1] = As[(m0 + g + 8) * 32 + kq0];
                af[mt][2] = As[(m0 + g    ) * 32 + kq1];
                af[mt][3] = As[(m0 + g + 8) * 32 + kq1];
            }
#pragma unroll
            for (int nt = 0; nt < 8; nt++) {
                const int n0 = wn + nt * 8;
                bf[nt][0] = Bs[(n0 + g) * 32 + kq0];
                bf[nt][1] = Bs[(n0 + g) * 32 + kq1];
            }
#pragma unroll
            for (int mt = 0; mt < 4; mt++)
#pragma unroll
                for (int nt = 0; nt < 8; nt++)
                    mma_f16(acc[mt][nt], af[mt], bf[nt]);
        }
        buf = (buf + 1) % GSTAGES;
    }

#pragma unroll
    for (int mt = 0; mt < 4; mt++) {
#pragma unroll
        for (int nt = 0; nt < 8; nt++) {
            const int row = bm + wm + mt * 16 + g;
            const int col = bn + wn + nt * 8 + 2 * tq;
            *(float2*)&C[(size_t)row * Nd + col]       = make_float2(acc[mt][nt][0], acc[mt][nt][1]);
            *(float2*)&C[(size_t)(row + 8) * Nd + col] = make_float2(acc[mt][nt][2], acc[mt][nt][3]);
        }
    }
}

// ---------------- Depthwise causal conv (K=4) + SiLU ----------------
__global__ void conv_silu_kernel(const float* __restrict__ conv_w, const float* __restrict__ conv_b)
{
    int idx = blockIdx.x * blockDim.x + threadIdx.x;
    if (idx >= LSEQ * DCONV) return;
    int t = idx / DCONV, c = idx % DCONV;
    float acc = conv_b[c];
    const float* w = conv_w + c * KCONV;
#pragma unroll
    for (int k = 0; k < KCONV; k++) {
        int tt = t + k - (KCONV - 1);
        if (tt >= 0) acc += w[k] * g_proj[(size_t)tt * DPROJ + DINTER + c];
    }
    g_xbc[idx] = fast_silu(acc);
}

// ---------------- dt softplus + per-chunk cumsum of A*dt ----------------
__global__ __launch_bounds__(CSZ) void dt_scan_kernel(
    const float* __restrict__ dt_bias, const float* __restrict__ A_log)
{
    int c = blockIdx.x, h = blockIdx.y, l = threadIdx.x;
    int t = c * CSZ + l;
    float raw = g_proj[(size_t)t * DPROJ + DINTER + DCONV + h] + dt_bias[h];
    float dtp = (raw > 0.f) ? (raw + log1pf(__expf(-raw))) : log1pf(__expf(raw));
    g_dt[t * NH + h] = dtp;
    float a = -__expf(A_log[h]) * dtp;

    __shared__ float s[CSZ];
    s[l] = a;
    __syncthreads();
#pragma unroll
    for (int off = 1; off < CSZ; off <<= 1) {
        float v = (l >= off) ? s[l - off] : 0.f;
        __syncthreads();
        s[l] += v;
        __syncthreads();
    }
    g_acs[(c * NH + h) * CSZ + l] = s[l];
    if (l == CSZ - 1) g_alast[c * NH + h] = s[l];
}

// ---------------- CBt[c][g][s][l] = sum_n C[l,n]*B[s,n] ----------------
__global__ __launch_bounds__(256) void cb_kernel()
{
    int c = blockIdx.x, g = blockIdx.y;
    int tid = threadIdx.x, tx = tid & 15, ty = tid >> 4;
    __shared__ float Csn[16][CSZ];
    __shared__ float Bsn[16][CSZ];
    float acc[8][8];
#pragma unroll
    for (int i = 0; i < 8; i++)
#pragma unroll
        for (int j = 0; j < 8; j++) acc[i][j] = 0.f;

    const float* Cg = g_xbc + DINTER + NG * DN + g * DN;
    const float* Bg = g_xbc + DINTER + g * DN;

    for (int n0 = 0; n0 < DN; n0 += 16) {
        for (int i = tid; i < CSZ * 4; i += 256) {
            int r = i >> 2, q = i & 3;
            const size_t row = (size_t)(c * CSZ + r) * DCONV + n0 + q * 4;
            float4 cv = *(const float4*)(Cg + row);
            float4 bv = *(const float4*)(Bg + row);
            Csn[q * 4 + 0][r] = cv.x; Csn[q * 4 + 1][r] = cv.y;
            Csn[q * 4 + 2][r] = cv.z; Csn[q * 4 + 3][r] = cv.w;
            Bsn[q * 4 + 0][r] = bv.x; Bsn[q * 4 + 1][r] = bv.y;
            Bsn[q * 4 + 2][r] = bv.z; Bsn[q * 4 + 3][r] = bv.w;
        }
        __syncthreads();
#pragma unroll
        for (int nn = 0; nn < 16; nn++) {
            float4 c0 = *(const float4*)&Csn[nn][tx * 8];
            float4 c1 = *(const float4*)&Csn[nn][tx * 8 + 4];
            float4 b0 = *(const float4*)&Bsn[nn][ty * 8];
            float4 b1 = *(const float4*)&Bsn[nn][ty * 8 + 4];
            float cl[8] = {c0.x, c0.y, c0.z, c0.w, c1.x, c1.y, c1.z, c1.w};
            float bs[8] = {b0.x, b0.y, b0.z, b0.w, b1.x, b1.y, b1.z, b1.w};
#pragma unroll
            for (int si = 0; si < 8; si++)
#pragma unroll
                for (int li = 0; li < 8; li++) acc[si][li] += cl[li] * bs[si];
        }
        __syncthreads();
    }
    float* out = g_cbt + (size_t)(c * NG + g) * CSZ * CSZ;
#pragma unroll
    for (int si = 0; si < 8; si++) {
        int s = ty * 8 + si;
        *(float4*)(out + (size_t)s * CSZ + tx * 8)     = make_float4(acc[si][0], acc[si][1], acc[si][2], acc[si][3]);
        *(float4*)(out + (size_t)s * CSZ + tx * 8 + 4) = make_float4(acc[si][4], acc[si][5], acc[si][6], acc[si][7]);
    }
}

// ---------------- Y_diag + D residual ----------------
__global__ __launch_bounds__(256) void ydiag_kernel(const float* __restrict__ Dparam)
{
    int c = blockIdx.x, h = blockIdx.y, g = h >> 4;
    int tid = threadIdx.x, tx = tid & 15, ty = tid >> 4;
    __shared__ float xs[CSZ][DP];
    __shared__ float Ms[CSZ][17];
    __shared__ float acsS[CSZ];
    __shared__ float dts[CSZ];

    for (int i = tid; i < CSZ * DP / 4; i += 256) {
        int r = i >> 4, q = i & 15;
        *(float4*)&xs[r][q * 4] =
            *(const float4*)(g_xbc + (size_t)(c * CSZ + r) * DCONV + h * DP + q * 4);
    }
    if (tid < CSZ) {
        dts[tid]  = g_dt[(c * CSZ + tid) * NH + h];
        acsS[tid] = g_acs[(c * NH + h) * CSZ + tid];
    }
    __syncthreads();

    float acc[8][4];
#pragma unroll
    for (int i = 0; i < 8; i++)
#pragma unroll
        for (int j = 0; j < 4; j++) acc[i][j] = 0.f;

    const float* cbBase = g_cbt + (size_t)(c * NG + g) * CSZ * CSZ;
    const int ss_row = tid >> 4;
    const int lg     = tid & 15;

    for (int s0 = 0; s0 < CSZ; s0 += 16) {
        {
            const int s = s0 + ss_row;
            const float as  = acsS[s];
            const float dsv = dts[s];
            const float* cbRow = cbBase + (size_t)s * CSZ;
#pragma unroll
            for (int k = 0; k < 8; k++) {
                const int l = lg * 8 + k;
                float f = 0.f;
                if (s <= l) f = cbRow[l] * __expf(acsS[l] - as) * dsv;
                Ms[l][ss_row] = f;
            }
        }
        __syncthreads();

#pragma unroll
        for (int ss = 0; ss < 16; ss++) {
            const int s = s0 + ss;
            float msv[8];
#pragma unroll
            for (int i = 0; i < 8; i++) msv[i] = Ms[ty * 8 + i][ss];
            float4 xv4 = *(const float4*)&xs[s][tx * 4];
#pragma unroll
            for (int i = 0; i < 8; i++) {
                acc[i][0] += msv[i] * xv4.x;
                acc[i][1] += msv[i] * xv4.y;
                acc[i][2] += msv[i] * xv4.z;
                acc[i][3] += msv[i] * xv4.w;
            }
        }
        __syncthreads();
    }

    const float dcoef = Dparam[h];
#pragma unroll
    for (int i = 0; i < 8; i++) {
        int l = ty * 8 + i;
        float4 xr = *(const float4*)&xs[l][tx * 4];
        float4 o = make_float4(acc[i][0] + dcoef * xr.x, acc[i][1] + dcoef * xr.y,
                               acc[i][2] + dcoef * xr.z, acc[i][3] + dcoef * xr.w);
        *(float4*)(g_y + (size_t)(c * CSZ + l) * DINTER + h * DP + tx * 4) = o;
    }
}

// ---------------- Local chunk states ----------------
__global__ __launch_bounds__(256) void states_kernel()
{
    int c = blockIdx.x, h = blockIdx.y, g = h >> 4;
    int tid = threadIdx.x, tx = tid & 15, ty = tid >> 4;
    __shared__ float Bsh[32][DN];
    __shared__ float xds[32][DP];
    __shared__ float dec[32];
    float acc[4][8];
#pragma unroll
    for (int i = 0; i < 4; i++)
#pragma unroll
        for (int j = 0; j < 8; j++) acc[i][j] = 0.f;

    const float al = g_alast[c * NH + h];
    for (int l0 = 0; l0 < CSZ; l0 += 32) {
        for (int i = tid; i < 32 * DN / 4; i += 256) {
            int r = i >> 5, q = i & 31;
            *(float4*)&Bsh[r][q * 4] = *(const float4*)(
                g_xbc + (size_t)(c * CSZ + l0 + r) * DCONV + DINTER + g * DN + q * 4);
        }
        for (int i = tid; i < 32 * DP / 4; i += 256) {
            int r = i >> 4, q = i & 15;
            int t = c * CSZ + l0 + r;
            float4 xv = *(const float4*)(g_xbc + (size_t)t * DCONV + h * DP + q * 4);
            float d = g_dt[t * NH + h];
            xv.x *= d; xv.y *= d; xv.z *= d; xv.w *= d;
            *(float4*)&xds[r][q * 4] = xv;
        }
        if (tid < 32) dec[tid] = __expf(al - g_acs[(c * NH + h) * CSZ + l0 + tid]);
        __syncthreads();
#pragma unroll 8
        for (int ll = 0; ll < 32; ll++) {
            float d = dec[ll];
            float4 b0 = *(const float4*)&Bsh[ll][tx * 8];
            float4 b1 = *(const float4*)&Bsh[ll][tx * 8 + 4];
            float bb[8] = {b0.x, b0.y, b0.z, b0.w, b1.x, b1.y, b1.z, b1.w};
            float4 xv = *(const float4*)&xds[ll][ty * 4];
            float xp[4] = {xv.x * d, xv.y * d, xv.z * d, xv.w * d};
#pragma unroll
            for (int pi = 0; pi < 4; pi++)
#pragma unroll
                for (int nj = 0; nj < 8; nj++) acc[pi][nj] += xp[pi] * bb[nj];
        }
        __syncthreads();
    }
    float* out = g_states + (size_t)(c * NH + h) * DP * DN;
#pragma unroll
    for (int pi = 0; pi < 4; pi++) {
        int p = ty * 4 + pi;
        *(float4*)(out + (size_t)p * DN + tx * 8)     = make_float4(acc[pi][0], acc[pi][1], acc[pi][2], acc[pi][3]);
        *(float4*)(out + (size_t)p * DN + tx * 8 + 4) = make_float4(acc[pi][4], acc[pi][5], acc[pi][6], acc[pi][7]);
    }
}

// ---------------- Inter-chunk scan ----------------
__global__ void prefix_kernel()
{
    int idx = blockIdx.x * blockDim.x + threadIdx.x;
    if (idx >= NH * DP * DN) return;
    int h = idx >> 13;
    float s = 0.f;
#pragma unroll
    for (int c = 0; c < NCH; c++) {
        size_t off = (size_t)c * NH * DP * DN + idx;
        g_prefix[off] = s;
        s = __expf(g_alast[c * NH + h]) * s + g_states[off];
    }
}

// ---------------- Y_off ----------------
__global__ __launch_bounds__(256) void yoff_kernel()
{
    int c = blockIdx.x, h = blockIdx.y, g = h >> 4;
    int tid = threadIdx.x, tx = tid & 15, ty = tid >> 4;
    __shared__ float Cs[CSZ][32];
    __shared__ float Pf[DP][33];
    __shared__ float acsS[CSZ];
    if (tid < CSZ) acsS[tid] = g_acs[(c * NH + h) * CSZ + tid];

    float acc[8][4];
#pragma unroll
    for (int i = 0; i < 8; i++)
#pragma unroll
        for (int j = 0; j < 4; j++) acc[i][j] = 0.f;

    for (int n0 = 0; n0 < DN; n0 += 32) {
        for (int i = tid; i < CSZ * 8; i += 256) {
            int r = i >> 3, q = i & 7;
            *(float4*)&Cs[r][q * 4] = *(const float4*)(
                g_xbc + (size_t)(c * CSZ + r) * DCONV + DINTER + NG * DN + g * DN + n0 + q * 4);
        }
        for (int i = tid; i < DP * 8; i += 256) {
            int r = i >> 3, q = i & 7;
            float4 v = *(const float4*)(
                g_prefix + ((size_t)(c * NH + h) * DP + r) * DN + n0 + q * 4);
            Pf[r][q * 4 + 0] = v.x; Pf[r][q * 4 + 1] = v.y;
            Pf[r][q * 4 + 2] = v.z; Pf[r][q * 4 + 3] = v.w;
        }
        __syncthreads();
#pragma unroll 8
        for (int nn = 0; nn < 32; nn++) {
            float cl[8], pv[4];
#pragma unroll
            for (int i = 0; i < 8; i++) cl[i] = Cs[ty * 8 + i][nn];
#pragma unroll
            for (int j = 0; j < 4; j++) pv[j] = Pf[tx * 4 + j][nn];
#pragma unroll
            for (int i = 0; i < 8; i++)
#pragma unroll
                for (int j = 0; j < 4; j++) acc[i][j] += cl[i] * pv[j];
        }
        __syncthreads();
    }
#pragma unroll
    for (int i = 0; i < 8; i++) {
        int l = ty * 8 + i;
        float e = __expf(acsS[l]);
        float* yp = g_y + (size_t)(c * CSZ + l) * DINTER + h * DP + tx * 4;
        float4 y = *(float4*)yp;
        y.x += e * acc[i][0]; y.y += e * acc[i][1];
        y.z += e * acc[i][2]; y.w += e * acc[i][3];
        *(float4*)yp = y;
    }
}

// ---------------- RMSNorm * norm_w * silu(gate); emits fp16 for GEMM2 ----------------
__global__ __launch_bounds__(256) void rms_gate_kernel(const float* __restrict__ norm_w)
{
    int t = blockIdx.x, tid = threadIdx.x;
    const size_t base = (size_t)t * DINTER;
    float ss = 0.f;
    for (int i = tid; i < DINTER; i += 256) {
        float v = g_y[base + i];
        ss += v * v;
    }
    __shared__ float red[256];
    red[tid] = ss;
    __syncthreads();
#pragma unroll
    for (int o = 128; o > 0; o >>= 1) {
        if (tid < o) red[tid] += red[tid + o];
        __syncthreads();
    }
    float inv = rsqrtf(red[0] / (float)DINTER + RMS_EPS);
    for (int i = tid; i < DINTER; i += 256) {
        float v = g_y[base + i] * inv * norm_w[i];
        v *= fast_silu(g_proj[(size_t)t * DPROJ + i]);
        g_yh[base + i] = __float2half_rn(v);
    }
}

// ---------------- Launch ----------------
extern "C" void kernel_launch(void* const* d_in, const int* in_sizes, int n_in,
                              void* d_out, int out_size)
{
    (void)in_sizes; (void)n_in; (void)out_size;
    const float* hs         = (const float*)d_in[0];
    const float* in_proj_w  = (const float*)d_in[1];
    const float* conv_w     = (const float*)d_in[2];
    const float* conv_b     = (const float*)d_in[3];
    const float* dt_bias    = (const float*)d_in[4];
    const float* A_log      = (const float*)d_in[5];
    const float* Dp         = (const float*)d_in[6];
    const float* norm_w     = (const float*)d_in[7];
    const float* out_proj_w = (const float*)d_in[8];
    float* out = (float*)d_out;

    void *p_proj = nullptr, *p_yh = nullptr, *p_hsth = nullptr, *p_w1th = nullptr, *p_w2th = nullptr;
    cudaGetSymbolAddress(&p_proj, g_proj);
    cudaGetSymbolAddress(&p_yh, g_yh);
    cudaGetSymbolAddress(&p_hsth, g_hsth);
    cudaGetSymbolAddress(&p_w1th, g_w1th);
    cudaGetSymbolAddress(&p_w2th, g_w2th);

    cudaFuncSetAttribute(gemm_f16_kernel, cudaFuncAttributeMaxDynamicSharedMemorySize, GEMM_DSMEM);

    // 0) pre-convert GEMM operands to fp16
    {
        int n4;
        n4 = LSEQ * DMODEL / 4;
        cvt_f16_kernel<<<(n4 + 255) / 256, 256>>>(hs, (__half*)p_hsth, n4);
        n4 = DPROJ * DMODEL / 4;
        cvt_f16_kernel<<<(n4 + 255) / 256, 256>>>(in_proj_w, (__half*)p_w1th, n4);
        n4 = DMODEL * DINTER / 4;
        cvt_f16_kernel<<<(n4 + 255) / 256, 256>>>(out_proj_w, (__half*)p_w2th, n4);
    }

    // 1) in-proj GEMM (fp16 tensor cores)
    gemm_f16_kernel<<<dim3(DPROJ / 128, LSEQ / 128), 128, GEMM_DSMEM>>>(
        (const __half*)p_hsth, (const __half*)p_w1th, (float*)p_proj, DPROJ, DMODEL);
    // 2) causal depthwise conv + silu
    conv_silu_kernel<<<(LSEQ * DCONV + 255) / 256, 256>>>(conv_w, conv_b);
    // 3) dt softplus + per-chunk cumsum of A*dt
    dt_scan_kernel<<<dim3(NCH, NH), CSZ>>>(dt_bias, A_log);
    // 4) C·B^T per (chunk, group)
    cb_kernel<<<dim3(NCH, NG), 256>>>();
    // 5) intra-chunk output + D residual
    ydiag_kernel<<<dim3(NCH, NH), 256>>>(Dp);
    // 6) local chunk states
    states_kernel<<<dim3(NCH, NH), 256>>>();
    // 7) inter-chunk state scan
    prefix_kernel<<<(NH * DP * DN + 255) / 256, 256>>>();
    // 8) off-diagonal output
    yoff_kernel<<<dim3(NCH, NH), 256>>>();
    // 9) gated RMSNorm (emits fp16)
    rms_gate_kernel<<<LSEQ, 256>>>(norm_w);
    // 10) out-proj GEMM (fp16)
    gemm_f16_kernel<<<dim3(DMODEL / 128, LSEQ / 128), 128, GEMM_DSMEM>>>(
        (const __half*)p_yh, (const __half*)p_w2th, out, DMODEL, DINTER);
}

// round 11
// speedup vs baseline: 2.1029x; 1.0038x over previous
#include <cuda_runtime.h>
#include <cuda_fp16.h>
#include <math.h>
#include <stdint.h>

// ---------------- Problem constants ----------------
#define LSEQ   2048
#define DMODEL 4096
#define NH     128
#define DP     64
#define NG     8
#define DN     128
#define CSZ    128
#define NCH    (LSEQ / CSZ)
#define KCONV  4
#define DINTER 8192
#define DCONV  10240
#define DPROJ  18560
#define RMS_EPS 1e-5f

// ---------------- Scratch ----------------
__device__ float g_proj[LSEQ * DPROJ];
__device__ float g_xbc[LSEQ * DCONV];
__device__ float g_dt[LSEQ * NH];
__device__ float g_acs[NCH * NH * CSZ];
__device__ float g_alast[NCH * NH];
__device__ float g_cbt[NCH * NG * CSZ * CSZ];
__device__ float g_states[NCH * NH * DP * DN];
__device__ float g_prefix[NCH * NH * DP * DN];
__device__ float g_y[LSEQ * DINTER];
// fp16 copies of GEMM operands
__device__ __half g_hsth[LSEQ * DMODEL];
__device__ __half g_w1th[DPROJ * DMODEL];
__device__ __half g_w2th[DMODEL * DINTER];
__device__ __half g_yh[LSEQ * DINTER];

// ---------------- helpers ----------------
__device__ __forceinline__ void mma_f16(float c[4], const uint32_t a[4], const uint32_t b[2]) {
    asm volatile(
        "mma.sync.aligned.m16n8k16.row.col.f32.f16.f16.f32 "
        "{%0,%1,%2,%3}, {%4,%5,%6,%7}, {%8,%9}, {%0,%1,%2,%3};"
        : "+f"(c[0]), "+f"(c[1]), "+f"(c[2]), "+f"(c[3])
        : "r"(a[0]), "r"(a[1]), "r"(a[2]), "r"(a[3]), "r"(b[0]), "r"(b[1]));
}
__device__ __forceinline__ float fast_silu(float x) {
    float t;
    asm("tanh.approx.f32 %0, %1;" : "=f"(t) : "f"(x * 0.5f));
    return 0.5f * x * (1.f + t);
}
__device__ __forceinline__ uint32_t smem_u32(const void* p) {
    uint32_t a;
    asm("{ .reg .u64 t; cvta.to.shared.u64 t, %1; cvt.u32.u64 %0, t; }" : "=r"(a) : "l"(p));
    return a;
}
__device__ __forceinline__ void cp_async16(uint32_t saddr, const void* gaddr) {
    asm volatile("cp.async.cg.shared.global [%0], [%1], 16;" :: "r"(saddr), "l"(gaddr));
}
#define CP_COMMIT() asm volatile("cp.async.commit_group;" ::: "memory")
#define CP_WAIT(n)  asm volatile("cp.async.wait_group %0;" :: "n"(n) : "memory")

// ---------------- fp32 -> fp16 pre-conversion ----------------
__global__ void cvt_f16_kernel(const float* __restrict__ in, __half* __restrict__ out, int n4)
{
    int i = blockIdx.x * blockDim.x + threadIdx.x;
    if (i >= n4) return;
    float4 v = ((const float4*)in)[i];
    __half2 h0 = __floats2half2_rn(v.x, v.y);
    __half2 h1 = __floats2half2_rn(v.z, v.w);
    uint2 o;
    o.x = *(uint32_t*)&h0;
    o.y = *(uint32_t*)&h1;
    ((uint2*)out)[i] = o;
}

// ---------------- fp16 GEMM: 128 threads, warp tile 64x64, BK=64, 3 stages ----------------
// C[M,Nd] = A[M,Kd]*B[Nd,Kd]^T. grid.x = M tiles (fast), grid.y = N tiles -> L2 reuse of B.
#define GSTAGES 3
#define STAGEW  (128 * 32)
#define GEMM_DSMEM (GSTAGES * 2 * STAGEW * 4)   // 98304 bytes

__global__ __launch_bounds__(128, 2) void gemm_f16_kernel(
    const __half* __restrict__ A, const __half* __restrict__ B, float* __restrict__ C,
    int Nd, int Kd)
{
    extern __shared__ float smf[];
    float* const Abuf = smf;
    float* const Bbuf = smf + GSTAGES * STAGEW;

    const int tid  = threadIdx.x;
    const int lane = tid & 31, warp = tid >> 5;
    const int wm = (warp >> 1) * 64;
    const int wn = (warp & 1) * 64;
    const int g  = lane >> 2, tq = lane & 3;
    const int bm = blockIdx.x * 128, bn = blockIdx.y * 128;   // M fast, N slow

    const int r0 = tid >> 3, c = tid & 7;
    const uint32_t swoff = (uint32_t)((c ^ (r0 & 7)) << 4);
    const __half* AgBase = A + (size_t)(bm + r0) * Kd + c * 8;
    const __half* BgBase = B + (size_t)(bn + r0) * Kd + c * 8;
    const uint32_t sA0 = smem_u32(Abuf) + (uint32_t)(r0 * 128) + swoff;
    const uint32_t sB0 = smem_u32(Bbuf) + (uint32_t)(r0 * 128) + swoff;

    const int KT = Kd >> 6;

#pragma unroll
    for (int s = 0; s < GSTAGES - 1; s++) {
        const uint32_t so = (uint32_t)(s * STAGEW * 4);
        const size_t ko = (size_t)s * 64;
#pragma unroll
        for (int j = 0; j < 8; j++) {
            cp_async16(sA0 + so + j * 16 * 128, AgBase + (size_t)(16 * j) * Kd + ko);
            cp_async16(sB0 + so + j * 16 * 128, BgBase + (size_t)(16 * j) * Kd + ko);
        }
        CP_COMMIT();
    }

    float acc[4][8][4];
#pragma unroll
    for (int mt = 0; mt < 4; mt++)
#pragma unroll
        for (int nt = 0; nt < 8; nt++)
#pragma unroll
            for (int qq = 0; qq < 4; qq++) acc[mt][nt][qq] = 0.f;

    int buf = 0;
    for (int kt = 0; kt < KT; kt++) {
        CP_WAIT(1);
        __syncthreads();

        const int pf = kt + GSTAGES - 1;
        if (pf < KT) {
            const int pb = pf % GSTAGES;
            const uint32_t so = (uint32_t)(pb * STAGEW * 4);
            const size_t ko = (size_t)pf * 64;
#pragma unroll
            for (int j = 0; j < 8; j++) {
                cp_async16(sA0 + so + j * 16 * 128, AgBase + (size_t)(16 * j) * Kd + ko);
                cp_async16(sB0 + so + j * 16 * 128, BgBase + (size_t)(16 * j) * Kd + ko);
            }
        }
        CP_COMMIT();

        const uint32_t* As = (const uint32_t*)(Abuf + buf * STAGEW);
        const uint32_t* Bs = (const uint32_t*)(Bbuf + buf * STAGEW);
#pragma unroll
        for (int ks = 0; ks < 4; ks++) {
            const int kq0 = ((2 * ks)     ^ g) * 4 + tq;
            const int kq1 = ((2 * ks + 1) ^ g) * 4 + tq;
            uint32_t af[4][4], bf[8][2];
#pragma unroll
            for (int mt = 0; mt < 4; mt++) {
                const int m0 = wm + mt * 16;
                af[mt][0] = As[(m0 + g    ) * 32 + kq0];
                af[mt][1] = As[(m0 + g + 8) * 32 + kq0];
                af[mt][2] = As[(m0 + g    ) * 32 + kq1];
                af[mt][3] = As[(m0 + g + 8) * 32 + kq1];
            }
#pragma unroll
            for (int nt = 0; nt < 8; nt++) {
                const int n0 = wn + nt * 8;
                bf[nt][0] = Bs[(n0 + g) * 32 + kq0];
                bf[nt][1] = Bs[(n0 + g) * 32 + kq1];
            }
#pragma unroll
            for (int mt = 0; mt < 4; mt++)
#pragma unroll
                for (int nt = 0; nt < 8; nt++)
                    mma_f16(acc[mt][nt], af[mt], bf[nt]);
        }
        buf = (buf + 1) % GSTAGES;
    }

#pragma unroll
    for (int mt = 0; mt < 4; mt++) {
#pragma unroll
        for (int nt = 0; nt < 8; nt++) {
            const int row = bm + wm + mt * 16 + g;
            const int col = bn + wn + nt * 8 + 2 * tq;
            *(float2*)&C[(size_t)row * Nd + col]       = make_float2(acc[mt][nt][0], acc[mt][nt][1]);
            *(float2*)&C[(size_t)(row + 8) * Nd + col] = make_float2(acc[mt][nt][2], acc[mt][nt][3]);
        }
    }
}

// ---------------- Depthwise causal conv (K=4) + SiLU ----------------
__global__ void conv_silu_kernel(const float* __restrict__ conv_w, const float* __restrict__ conv_b)
{
    int idx = blockIdx.x * blockDim.x + threadIdx.x;
    if (idx >= LSEQ * DCONV) return;
    int t = idx / DCONV, c = idx % DCONV;
    float acc = conv_b[c];
    const float* w = conv_w + c * KCONV;
#pragma unroll
    for (int k = 0; k < KCONV; k++) {
        int tt = t + k - (KCONV - 1);
        if (tt >= 0) acc += w[k] * g_proj[(size_t)tt * DPROJ + DINTER + c];
    }
    g_xbc[idx] = fast_silu(acc);
}

// ---------------- dt softplus + per-chunk cumsum of A*dt ----------------
__global__ __launch_bounds__(CSZ) void dt_scan_kernel(
    const float* __restrict__ dt_bias, const float* __restrict__ A_log)
{
    int c = blockIdx.x, h = blockIdx.y, l = threadIdx.x;
    int t = c * CSZ + l;
    float raw = g_proj[(size_t)t * DPROJ + DINTER + DCONV + h] + dt_bias[h];
    float dtp = (raw > 0.f) ? (raw + log1pf(__expf(-raw))) : log1pf(__expf(raw));
    g_dt[t * NH + h] = dtp;
    float a = -__expf(A_log[h]) * dtp;

    __shared__ float s[CSZ];
    s[l] = a;
    __syncthreads();
#pragma unroll
    for (int off = 1; off < CSZ; off <<= 1) {
        float v = (l >= off) ? s[l - off] : 0.f;
        __syncthreads();
        s[l] += v;
        __syncthreads();
    }
    g_acs[(c * NH + h) * CSZ + l] = s[l];
    if (l == CSZ - 1) g_alast[c * NH + h] = s[l];
}

// ---------------- CBt[c][g][s][l] = sum_n C[l,n]*B[s,n] ----------------
__global__ __launch_bounds__(256) void cb_kernel()
{
    int c = blockIdx.x, g = blockIdx.y;
    int tid = threadIdx.x, tx = tid & 15, ty = tid >> 4;
    __shared__ float Csn[16][CSZ];
    __shared__ float Bsn[16][CSZ];
    float acc[8][8];
#pragma unroll
    for (int i = 0; i < 8; i++)
#pragma unroll
        for (int j = 0; j < 8; j++) acc[i][j] = 0.f;

    const float* Cg = g_xbc + DINTER + NG * DN + g * DN;
    const float* Bg = g_xbc + DINTER + g * DN;

    for (int n0 = 0; n0 < DN; n0 += 16) {
        for (int i = tid; i < CSZ * 4; i += 256) {
            int r = i >> 2, q = i & 3;
            const size_t row = (size_t)(c * CSZ + r) * DCONV + n0 + q * 4;
            float4 cv = *(const float4*)(Cg + row);
            float4 bv = *(const float4*)(Bg + row);
            Csn[q * 4 + 0][r] = cv.x; Csn[q * 4 + 1][r] = cv.y;
            Csn[q * 4 + 2][r] = cv.z; Csn[q * 4 + 3][r] = cv.w;
            Bsn[q * 4 + 0][r] = bv.x; Bsn[q * 4 + 1][r] = bv.y;
            Bsn[q * 4 + 2][r] = bv.z; Bsn[q * 4 + 3][r] = bv.w;
        }
        __syncthreads();
#pragma unroll
        for (int nn = 0; nn < 16; nn++) {
            float4 c0 = *(const float4*)&Csn[nn][tx * 8];
            float4 c1 = *(const float4*)&Csn[nn][tx * 8 + 4];
            float4 b0 = *(const float4*)&Bsn[nn][ty * 8];
            float4 b1 = *(const float4*)&Bsn[nn][ty * 8 + 4];
            float cl[8] = {c0.x, c0.y, c0.z, c0.w, c1.x, c1.y, c1.z, c1.w};
            float bs[8] = {b0.x, b0.y, b0.z, b0.w, b1.x, b1.y, b1.z, b1.w};
#pragma unroll
            for (int si = 0; si < 8; si++)
#pragma unroll
                for (int li = 0; li < 8; li++) acc[si][li] += cl[li] * bs[si];
        }
        __syncthreads();
    }
    float* out = g_cbt + (size_t)(c * NG + g) * CSZ * CSZ;
#pragma unroll
    for (int si = 0; si < 8; si++) {
        int s = ty * 8 + si;
        *(float4*)(out + (size_t)s * CSZ + tx * 8)     = make_float4(acc[si][0], acc[si][1], acc[si][2], acc[si][3]);
        *(float4*)(out + (size_t)s * CSZ + tx * 8 + 4) = make_float4(acc[si][4], acc[si][5], acc[si][6], acc[si][7]);
    }
}

// ---------------- Y_diag + D residual (factorized decay exps) ----------------
// exp(acs_l - acs_s) = exp(acs_l - acs_s0) * exp(acs_s0 - acs_s); first factor
// underflows gracefully for distant l (true value < 1e-26, negligible).
__global__ __launch_bounds__(256) void ydiag_kernel(const float* __restrict__ Dparam)
{
    int c = blockIdx.x, h = blockIdx.y, g = h >> 4;
    int tid = threadIdx.x, tx = tid & 15, ty = tid >> 4;
    __shared__ float xs[CSZ][DP];
    __shared__ float Ms[CSZ][17];
    __shared__ float acsS[CSZ];
    __shared__ float dts[CSZ];
    __shared__ float el[CSZ];      // exp(acs_l - acs_s0)
    __shared__ float esd[16];      // exp(acs_s0 - acs_s) * dt_s

    for (int i = tid; i < CSZ * DP / 4; i += 256) {
        int r = i >> 4, q = i & 15;
        *(float4*)&xs[r][q * 4] =
            *(const float4*)(g_xbc + (size_t)(c * CSZ + r) * DCONV + h * DP + q * 4);
    }
    if (tid < CSZ) {
        dts[tid]  = g_dt[(c * CSZ + tid) * NH + h];
        acsS[tid] = g_acs[(c * NH + h) * CSZ + tid];
    }
    __syncthreads();

    float acc[8][4];
#pragma unroll
    for (int i = 0; i < 8; i++)
#pragma unroll
        for (int j = 0; j < 4; j++) acc[i][j] = 0.f;

    const float* cbBase = g_cbt + (size_t)(c * NG + g) * CSZ * CSZ;
    const int ss_row = tid >> 4;
    const int lg     = tid & 15;

    for (int s0 = 0; s0 < CSZ; s0 += 16) {
        // factor precompute: ~144 exps per tile instead of 2048
        const float a0 = acsS[s0];
        if (tid < CSZ) el[tid] = __expf(acsS[tid] - a0);
        else if (tid < CSZ + 16) {
            int s = s0 + (tid - CSZ);
            esd[tid - CSZ] = __expf(a0 - acsS[s]) * dts[s];
        }
        __syncthreads();

        {
            const int s = s0 + ss_row;
            const float fs = esd[ss_row];
            const float* cbRow = cbBase + (size_t)s * CSZ;
#pragma unroll
            for (int k = 0; k < 8; k++) {
                const int l = lg * 8 + k;
                Ms[l][ss_row] = (s <= l) ? cbRow[l] * el[l] * fs : 0.f;
            }
        }
        __syncthreads();

#pragma unroll
        for (int ss = 0; ss < 16; ss++) {
            const int s = s0 + ss;
            float msv[8];
#pragma unroll
            for (int i = 0; i < 8; i++) msv[i] = Ms[ty * 8 + i][ss];
            float4 xv4 = *(const float4*)&xs[s][tx * 4];
#pragma unroll
            for (int i = 0; i < 8; i++) {
                acc[i][0] += msv[i] * xv4.x;
                acc[i][1] += msv[i] * xv4.y;
                acc[i][2] += msv[i] * xv4.z;
                acc[i][3] += msv[i] * xv4.w;
            }
        }
        __syncthreads();
    }

    const float dcoef = Dparam[h];
#pragma unroll
    for (int i = 0; i < 8; i++) {
        int l = ty * 8 + i;
        float4 xr = *(const float4*)&xs[l][tx * 4];
        float4 o = make_float4(acc[i][0] + dcoef * xr.x, acc[i][1] + dcoef * xr.y,
                               acc[i][2] + dcoef * xr.z, acc[i][3] + dcoef * xr.w);
        *(float4*)(g_y + (size_t)(c * CSZ + l) * DINTER + h * DP + tx * 4) = o;
    }
}

// ---------------- Local chunk states ----------------
__global__ __launch_bounds__(256) void states_kernel()
{
    int c = blockIdx.x, h = blockIdx.y, g = h >> 4;
    int tid = threadIdx.x, tx = tid & 15, ty = tid >> 4;
    __shared__ float Bsh[32][DN];
    __shared__ float xds[32][DP];
    __shared__ float dec[32];
    float acc[4][8];
#pragma unroll
    for (int i = 0; i < 4; i++)
#pragma unroll
        for (int j = 0; j < 8; j++) acc[i][j] = 0.f;

    const float al = g_alast[c * NH + h];
    for (int l0 = 0; l0 < CSZ; l0 += 32) {
        for (int i = tid; i < 32 * DN / 4; i += 256) {
            int r = i >> 5, q = i & 31;
            *(float4*)&Bsh[r][q * 4] = *(const float4*)(
                g_xbc + (size_t)(c * CSZ + l0 + r) * DCONV + DINTER + g * DN + q * 4);
        }
        for (int i = tid; i < 32 * DP / 4; i += 256) {
            int r = i >> 4, q = i & 15;
            int t = c * CSZ + l0 + r;
            float4 xv = *(const float4*)(g_xbc + (size_t)t * DCONV + h * DP + q * 4);
            float d = g_dt[t * NH + h];
            xv.x *= d; xv.y *= d; xv.z *= d; xv.w *= d;
            *(float4*)&xds[r][q * 4] = xv;
        }
        if (tid < 32) dec[tid] = __expf(al - g_acs[(c * NH + h) * CSZ + l0 + tid]);
        __syncthreads();
#pragma unroll 8
        for (int ll = 0; ll < 32; ll++) {
            float d = dec[ll];
            float4 b0 = *(const float4*)&Bsh[ll][tx * 8];
            float4 b1 = *(const float4*)&Bsh[ll][tx * 8 + 4];
            float bb[8] = {b0.x, b0.y, b0.z, b0.w, b1.x, b1.y, b1.z, b1.w};
            float4 xv = *(const float4*)&xds[ll][ty * 4];
            float xp[4] = {xv.x * d, xv.y * d, xv.z * d, xv.w * d};
#pragma unroll
            for (int pi = 0; pi < 4; pi++)
#pragma unroll
                for (int nj = 0; nj < 8; nj++) acc[pi][nj] += xp[pi] * bb[nj];
        }
        __syncthreads();
    }
    float* out = g_states + (size_t)(c * NH + h) * DP * DN;
#pragma unroll
    for (int pi = 0; pi < 4; pi++) {
        int p = ty * 4 + pi;
        *(float4*)(out + (size_t)p * DN + tx * 8)     = make_float4(acc[pi][0], acc[pi][1], acc[pi][2], acc[pi][3]);
        *(float4*)(out + (size_t)p * DN + tx * 8 + 4) = make_float4(acc[pi][4], acc[pi][5], acc[pi][6], acc[pi][7]);
    }
}

// ---------------- Inter-chunk scan ----------------
__global__ void prefix_kernel()
{
    int idx = blockIdx.x * blockDim.x + threadIdx.x;
    if (idx >= NH * DP * DN) return;
    int h = idx >> 13;
    float s = 0.f;
#pragma unroll
    for (int c = 0; c < NCH; c++) {
        size_t off = (size_t)c * NH * DP * DN + idx;
        g_prefix[off] = s;
        s = __expf(g_alast[c * NH + h]) * s + g_states[off];
    }
}

// ---------------- Y_off ----------------
__global__ __launch_bounds__(256) void yoff_kernel()
{
    int c = blockIdx.x, h = blockIdx.y, g = h >> 4;
    int tid = threadIdx.x, tx = tid & 15, ty = tid >> 4;
    __shared__ float Cs[CSZ][32];
    __shared__ float Pf[DP][33];
    __shared__ float acsS[CSZ];
    if (tid < CSZ) acsS[tid] = g_acs[(c * NH + h) * CSZ + tid];

    float acc[8][4];
#pragma unroll
    for (int i = 0; i < 8; i++)
#pragma unroll
        for (int j = 0; j < 4; j++) acc[i][j] = 0.f;

    for (int n0 = 0; n0 < DN; n0 += 32) {
        for (int i = tid; i < CSZ * 8; i += 256) {
            int r = i >> 3, q = i & 7;
            *(float4*)&Cs[r][q * 4] = *(const float4*)(
                g_xbc + (size_t)(c * CSZ + r) * DCONV + DINTER + NG * DN + g * DN + n0 + q * 4);
        }
        for (int i = tid; i < DP * 8; i += 256) {
            int r = i >> 3, q = i & 7;
            float4 v = *(const float4*)(
                g_prefix + ((size_t)(c * NH + h) * DP + r) * DN + n0 + q * 4);
            Pf[r][q * 4 + 0] = v.x; Pf[r][q * 4 + 1] = v.y;
            Pf[r][q * 4 + 2] = v.z; Pf[r][q * 4 + 3] = v.w;
        }
        __syncthreads();
#pragma unroll 8
        for (int nn = 0; nn < 32; nn++) {
            float cl[8], pv[4];
#pragma unroll
            for (int i = 0; i < 8; i++) cl[i] = Cs[ty * 8 + i][nn];
#pragma unroll
            for (int j = 0; j < 4; j++) pv[j] = Pf[tx * 4 + j][nn];
#pragma unroll
            for (int i = 0; i < 8; i++)
#pragma unroll
                for (int j = 0; j < 4; j++) acc[i][j] += cl[i] * pv[j];
        }
        __syncthreads();
    }
#pragma unroll
    for (int i = 0; i < 8; i++) {
        int l = ty * 8 + i;
        float e = __expf(acsS[l]);
        float* yp = g_y + (size_t)(c * CSZ + l) * DINTER + h * DP + tx * 4;
        float4 y = *(float4*)yp;
        y.x += e * acc[i][0]; y.y += e * acc[i][1];
        y.z += e * acc[i][2]; y.w += e * acc[i][3];
        *(float4*)yp = y;
    }
}

// ---------------- RMSNorm * norm_w * silu(gate); emits fp16 for GEMM2 ----------------
__global__ __launch_bounds__(256) void rms_gate_kernel(const float* __restrict__ norm_w)
{
    int t = blockIdx.x, tid = threadIdx.x;
    const size_t base = (size_t)t * DINTER;
    float ss = 0.f;
    for (int i = tid; i < DINTER; i += 256) {
        float v = g_y[base + i];
        ss += v * v;
    }
    __shared__ float red[256];
    red[tid] = ss;
    __syncthreads();
#pragma unroll
    for (int o = 128; o > 0; o >>= 1) {
        if (tid < o) red[tid] += red[tid + o];
        __syncthreads();
    }
    float inv = rsqrtf(red[0] / (float)DINTER + RMS_EPS);
    for (int i = tid; i < DINTER; i += 256) {
        float v = g_y[base + i] * inv * norm_w[i];
        v *= fast_silu(g_proj[(size_t)t * DPROJ + i]);
        g_yh[base + i] = __float2half_rn(v);
    }
}

// ---------------- Launch ----------------
extern "C" void kernel_launch(void* const* d_in, const int* in_sizes, int n_in,
                              void* d_out, int out_size)
{
    (void)in_sizes; (void)n_in; (void)out_size;
    const float* hs         = (const float*)d_in[0];
    const float* in_proj_w  = (const float*)d_in[1];
    const float* conv_w     = (const float*)d_in[2];
    const float* conv_b     = (const float*)d_in[3];
    const float* dt_bias    = (const float*)d_in[4];
    const float* A_log      = (const float*)d_in[5];
    const float* Dp         = (const float*)d_in[6];
    const float* norm_w     = (const float*)d_in[7];
    const float* out_proj_w = (const float*)d_in[8];
    float* out = (float*)d_out;

    void *p_proj = nullptr, *p_yh = nullptr, *p_hsth = nullptr, *p_w1th = nullptr, *p_w2th = nullptr;
    cudaGetSymbolAddress(&p_proj, g_proj);
    cudaGetSymbolAddress(&p_yh, g_yh);
    cudaGetSymbolAddress(&p_hsth, g_hsth);
    cudaGetSymbolAddress(&p_w1th, g_w1th);
    cudaGetSymbolAddress(&p_w2th, g_w2th);

    cudaFuncSetAttribute(gemm_f16_kernel, cudaFuncAttributeMaxDynamicSharedMemorySize, GEMM_DSMEM);

    // 0) pre-convert GEMM operands to fp16
    {
        int n4;
        n4 = LSEQ * DMODEL / 4;
        cvt_f16_kernel<<<(n4 + 255) / 256, 256>>>(hs, (__half*)p_hsth, n4);
        n4 = DPROJ * DMODEL / 4;
        cvt_f16_kernel<<<(n4 + 255) / 256, 256>>>(in_proj_w, (__half*)p_w1th, n4);
        n4 = DMODEL * DINTER / 4;
        cvt_f16_kernel<<<(n4 + 255) / 256, 256>>>(out_proj_w, (__half*)p_w2th, n4);
    }

    // 1) in-proj GEMM (fp16, M-fast raster for B reuse in L2)
    gemm_f16_kernel<<<dim3(LSEQ / 128, DPROJ / 128), 128, GEMM_DSMEM>>>(
        (const __half*)p_hsth, (const __half*)p_w1th, (float*)p_proj, DPROJ, DMODEL);
    // 2) causal depthwise conv + silu
    conv_silu_kernel<<<(LSEQ * DCONV + 255) / 256, 256>>>(conv_w, conv_b);
    // 3) dt softplus + per-chunk cumsum of A*dt
    dt_scan_kernel<<<dim3(NCH, NH), CSZ>>>(dt_bias, A_log);
    // 4) C·B^T per (chunk, group)
    cb_kernel<<<dim3(NCH, NG), 256>>>();
    // 5) intra-chunk output + D residual
    ydiag_kernel<<<dim3(NCH, NH), 256>>>(Dp);
    // 6) local chunk states
    states_kernel<<<dim3(NCH, NH), 256>>>();
    // 7) inter-chunk state scan
    prefix_kernel<<<(NH * DP * DN + 255) / 256, 256>>>();
    // 8) off-diagonal output
    yoff_kernel<<<dim3(NCH, NH), 256>>>();
    // 9) gated RMSNorm (emits fp16)
    rms_gate_kernel<<<LSEQ, 256>>>(norm_w);
    // 10) out-proj GEMM (fp16, M-fast raster)
    gemm_f16_kernel<<<dim3(LSEQ / 128, DMODEL / 128), 128, GEMM_DSMEM>>>(
        (const __half*)p_yh, (const __half*)p_w2th, out, DMODEL, DINTER);
}